// round 13
// baseline (speedup 1.0000x reference)
#include <cuda_runtime.h>
#include <cuda_fp16.h>
#include <math.h>
#include <stdint.h>

// Problem constants
static constexpr int B = 2, S = 2048, D = 2048;
static constexpr int H = 16, KVH = 4, HD = 128;
static constexpr int MROWS = B * S;            // 4096
static constexpr int WINDOW = 512, GLOBALK = 64;
static constexpr float SCALE = 0.08838834764831845f;  // 1/sqrt(128)

// ------------- scratch (device globals) -------------
__device__ float g_q [(size_t)MROWS * (H * HD)];
__device__ float g_k [(size_t)MROWS * (KVH * HD)];
__device__ float g_v [(size_t)MROWS * (KVH * HD)];

__device__ __half g_xh[(size_t)MROWS * D];
__device__ __half g_wh[12189696];
__device__ __half g_wl[12189696];
__device__ __half g_th[(size_t)MROWS * 384];
__device__ __half g_aoh[(size_t)MROWS * (H * HD)];
__device__ __half g_qh[(size_t)MROWS * (H * HD)];
__device__ __half g_kh[(size_t)MROWS * (KVH * HD)];
__device__ __half g_vh[(size_t)MROWS * (KVH * HD)];

// weight pool layout (elements)
static constexpr size_t OFF_QKVW = 0;
static constexpr size_t OFF_QB   = 7077888;
static constexpr size_t OFF_OW   = 7471104;
static constexpr size_t OFF_OB   = 11927552;

// ============================================================
// helpers
// ============================================================
__device__ __forceinline__ uint32_t smem_u32(const void* p) {
    uint32_t a;
    asm("{ .reg .u64 t; cvta.to.shared.u64 t, %1; cvt.u32.u64 %0, t; }"
        : "=r"(a) : "l"(p));
    return a;
}
__device__ __forceinline__ void ldm_x4(uint32_t* r, uint32_t addr) {
    asm volatile("ldmatrix.sync.aligned.m8n8.x4.shared.b16 {%0,%1,%2,%3}, [%4];"
                 : "=r"(r[0]), "=r"(r[1]), "=r"(r[2]), "=r"(r[3]) : "r"(addr));
}
__device__ __forceinline__ void ldm_x4_t(uint32_t* r, uint32_t addr) {
    asm volatile("ldmatrix.sync.aligned.m8n8.x4.trans.shared.b16 {%0,%1,%2,%3}, [%4];"
                 : "=r"(r[0]), "=r"(r[1]), "=r"(r[2]), "=r"(r[3]) : "r"(addr));
}
__device__ __forceinline__ void mma16816(float* c, const uint32_t* a, const uint32_t* b) {
    asm volatile(
        "mma.sync.aligned.m16n8k16.row.col.f32.f16.f16.f32 "
        "{%0,%1,%2,%3}, {%4,%5,%6,%7}, {%8,%9}, {%0,%1,%2,%3};"
        : "+f"(c[0]), "+f"(c[1]), "+f"(c[2]), "+f"(c[3])
        : "r"(a[0]), "r"(a[1]), "r"(a[2]), "r"(a[3]), "r"(b[0]), "r"(b[1]));
}
#define CP16(saddr, gptr) \
    asm volatile("cp.async.cg.shared.global [%0], [%1], 16;" :: "r"(saddr), "l"(gptr))
#define CP_COMMIT() asm volatile("cp.async.commit_group;" ::: "memory")
#define CP_WAIT0()  asm volatile("cp.async.wait_group 0;" ::: "memory")
#define CP_WAIT1()  asm volatile("cp.async.wait_group 1;" ::: "memory")

__device__ __forceinline__ uint32_t packh2(float x, float y) {
    __half2 h = __floats2half2_rn(x, y);
    return *(uint32_t*)&h;
}
__device__ __forceinline__ void splith(float x, float y, uint32_t& h, uint32_t& l) {
    __half hx = __float2half_rn(x), hy = __float2half_rn(y);
    __half lx = __float2half_rn(x - __half2float(hx));
    __half ly = __float2half_rn(y - __half2float(hy));
    uint16_t uhx = *(uint16_t*)&hx, uhy = *(uint16_t*)&hy;
    uint16_t ulx = *(uint16_t*)&lx, uly = *(uint16_t*)&ly;
    h = (uint32_t)uhx | ((uint32_t)uhy << 16);
    l = (uint32_t)ulx | ((uint32_t)uly << 16);
}

// ============================================================
// converters
// ============================================================
__global__ void cvtx_kernel(const float* __restrict__ x,
                            __half* __restrict__ hi, int n4)
{
    int i = blockIdx.x * 256 + threadIdx.x;
    if (i >= n4) return;
    float4 v = ((const float4*)x)[i];
    __half h[4] = { __float2half_rn(v.x), __float2half_rn(v.y),
                    __float2half_rn(v.z), __float2half_rn(v.w) };
    *(uint2*)&hi[4*(size_t)i] = *(uint2*)h;
}

__global__ void cvtw_kernel(
    const float* p0, const float* p1, const float* p2, const float* p3,
    const float* p4, const float* p5, const float* p6, const float* p7,
    const float* p8, const float* p9, const float* p10, const float* p11,
    __half* __restrict__ hi, __half* __restrict__ lo)
{
    const float* srcs[12] = {p0,p1,p2,p3,p4,p5,p6,p7,p8,p9,p10,p11};
    const int pre[13] = {0, 1048576, 1114112, 1179648, 1441792, 1507328,
                         1523712, 1785856, 1851392, 1867776, 2916352,
                         2981888, 3047424};
    const int dst[12] = {0, 1572864, 1769472, 1048576, 1638400, 1835008,
                         1310720, 1703936, 1851392, 1867776, 2916352, 2981888};
    int gi = blockIdx.x * 256 + threadIdx.x;
    if (gi >= 3047424) return;
    int s = 0;
#pragma unroll
    for (int t = 1; t < 12; t++) if (gi >= pre[t]) s = t;
    int local = gi - pre[s];
    float4 v = ((const float4*)srcs[s])[local];
    uint32_t h01, l01, h23, l23;
    splith(v.x, v.y, h01, l01);
    splith(v.z, v.w, h23, l23);
    size_t o = 4 * ((size_t)dst[s] + local);
    *(uint32_t*)&hi[o]   = h01; *(uint32_t*)&hi[o+2] = h23;
    *(uint32_t*)&lo[o]   = l01; *(uint32_t*)&lo[o+2] = l23;
}

// ============================================================
// fused RoPE (+scale) + fp16 convert (hi only)
// ============================================================
__global__ void rope_split_kernel(const float* __restrict__ t,
                                  __half* __restrict__ hi,
                                  int heads, float scale, int total)
{
    int idx = blockIdx.x * 256 + threadIdx.x;
    if (idx >= total) return;
    int d   = idx & 63;
    int r   = idx >> 6;
    int s   = (r / heads) & (S - 1);
    double invf = pow(1.0e6, -(double)d / 64.0);
    float ang = (float)s * (float)invf;
    float sn, cs;
    sincosf(ang, &sn, &cs);
    const float* p = t + (size_t)r * 128 + 2 * d;
    float xr = p[0], xi = p[1];
    float o0 = (xr * cs - xi * sn) * scale;
    float o1 = (xr * sn + xi * cs) * scale;
    *(uint32_t*)&hi[(size_t)r * 128 + 2 * d] = packh2(o0, o1);
}

// ============================================================
// mma.sync GEMM v3: 128x128 CTA, 4 warps (2x2 of 64x64 tiles),
// 128 threads, 2 CTAs/SM. K-chunk 32, 2-stage cp.async.
// Register pipelining: A+B-hi frags double-buffered one kk ahead,
// B-lo loaded JIT (hidden under hi-HMMA block).
// LDSM traffic: 0.046 B/MAC (vs 0.094 before) -> SMEM ceiling ~68%.
// MODE 1 (QKVA) / 2 (BPROJ) / 3 (OUT) / 4 (ACC).
// ============================================================
template<int MODE>
__global__ void __launch_bounds__(128, 2) gemm_mma(
    const __half* __restrict__ Ahi, const int lda,
    const __half* __restrict__ Bhi, const __half* __restrict__ Blo, const int ldb,
    float* __restrict__ F0, float* __restrict__ F1, float* __restrict__ F2,
    __half* __restrict__ H0,
    const int M, const int N, const int K)
{
    constexpr int BM = 128, BN = 128;
    constexpr int NTHR = 128, MT = 4, NT = 8;
    constexpr int ASZ = BM * 40, BSZ = BN * 40;  // halves
    constexpr int STG = ASZ + 2 * BSZ;           // 15360 halves/stage
    extern __shared__ char dynsm[];
    __half* smem = (__half*)dynsm;

    const int tid = threadIdx.x, lane = tid & 31, warp = tid >> 5;
    const int bm = blockIdx.y * BM;
    const int bn = blockIdx.x * BN;
    const int wm0 = (warp >> 1) * 64, wn0 = (warp & 1) * 64;
    const uint32_t su = smem_u32(smem);

    const __half* Aptr = Ahi;
    if constexpr (MODE == 2)
        Aptr = Ahi + ((bn < 2048) ? 0 : (bn < 2560 ? 128 : 256));

    const int rowA = ((lane >> 3) & 1) * 8 + (lane & 7);
    const int kselA = (lane >> 4) * 8;
    const int rowB = ((lane >> 4) & 1) * 8 + (lane & 7);
    const int kselB = ((lane >> 3) & 1) * 8;

    float acc[MT][NT][4];
#pragma unroll
    for (int i = 0; i < MT; i++)
#pragma unroll
        for (int j = 0; j < NT; j++)
#pragma unroll
            for (int t = 0; t < 4; t++) acc[i][j][t] = 0.f;

    auto load_stage = [&](int st, int k0) {
        uint32_t base = su + (uint32_t)st * STG * 2;
#pragma unroll
        for (int c = tid; c < BM * 4; c += NTHR) {
            int r = c >> 2, sg = c & 3;
            uint32_t so = (uint32_t)(r * 80 + sg * 16);
            size_t ga = (size_t)(bm + r) * lda + k0 + sg * 8;
            CP16(base + so, Aptr + ga);
        }
#pragma unroll
        for (int c = tid; c < BN * 4; c += NTHR) {
            int r = c >> 2, sg = c & 3;
            uint32_t so = (uint32_t)(r * 80 + sg * 16);
            size_t gb = (size_t)(bn + r) * ldb + k0 + sg * 8;
            CP16(base + ASZ * 2 + so, Bhi + gb);
            CP16(base + (ASZ + BSZ) * 2 + so, Blo + gb);
        }
    };

    // frag registers: A + B-hi double-buffered, B-lo single (JIT)
    uint32_t ah[2][MT][4], bh[2][NT][2], bl[NT][2];

    const int nk = K / 32;
    load_stage(0, 0);
    CP_COMMIT();

    for (int kt = 0; kt < nk; kt++) {
        const int buf = kt & 1;
        if (kt + 1 < nk) {
            load_stage((kt + 1) & 1, (kt + 1) * 32);
            CP_COMMIT();
            CP_WAIT1();
        } else {
            CP_WAIT0();
        }
        __syncthreads();

        const uint32_t uAh = su + (uint32_t)buf * STG * 2;
        const uint32_t uBh = uAh + ASZ * 2;
        const uint32_t uBl = uAh + (ASZ + BSZ) * 2;

        auto ldAB = [&](int kk, int pb) {
#pragma unroll
            for (int mt = 0; mt < MT; mt++) {
                uint32_t off = (uint32_t)((wm0 + mt*16 + rowA) * 40 + kk*16 + kselA) * 2;
                ldm_x4(ah[pb][mt], uAh + off);
            }
#pragma unroll
            for (int g = 0; g < 4; g++) {
                uint32_t off = (uint32_t)((wn0 + g*16 + rowB) * 40 + kk*16 + kselB) * 2;
                uint32_t r4[4];
                ldm_x4(r4, uBh + off);
                bh[pb][2*g][0] = r4[0]; bh[pb][2*g][1] = r4[1];
                bh[pb][2*g+1][0] = r4[2]; bh[pb][2*g+1][1] = r4[3];
            }
        };
        auto ldBlo = [&](int kk) {
#pragma unroll
            for (int g = 0; g < 4; g++) {
                uint32_t off = (uint32_t)((wn0 + g*16 + rowB) * 40 + kk*16 + kselB) * 2;
                uint32_t r4[4];
                ldm_x4(r4, uBl + off);
                bl[2*g][0] = r4[0]; bl[2*g][1] = r4[1];
                bl[2*g+1][0] = r4[2]; bl[2*g+1][1] = r4[3];
            }
        };

        ldAB(0, 0);
#pragma unroll
        for (int kk = 0; kk < 2; kk++) {
            const int pb = kk & 1;
            ldBlo(kk);                       // JIT: hidden under hi-HMMA below
            if (kk < 1) ldAB(1, 1);          // next kk's A + B-hi
#pragma unroll
            for (int mt = 0; mt < MT; mt++)
#pragma unroll
                for (int nt = 0; nt < NT; nt++)
                    mma16816(acc[mt][nt], ah[pb][mt], bh[pb][nt]);
#pragma unroll
            for (int mt = 0; mt < MT; mt++)
#pragma unroll
                for (int nt = 0; nt < NT; nt++)
                    mma16816(acc[mt][nt], ah[pb][mt], bl[nt]);
        }
        __syncthreads();
    }

    // ---- epilogue: CTA-uniform routing ----
    const int crow = lane >> 2, ccol = (lane & 3) * 2;
    float* Cf = nullptr;  __half *Sh = nullptr;
    int ldc = 0, ldcs = 0, col0 = bn;
    bool doAcc = false, doWF = false, doSH = false;

    if constexpr (MODE == 1) {
        if (bn < 2048)      { Cf = F0; ldc = 2048; col0 = bn;        doWF = true; }
        else if (bn < 2560) { Cf = F1; ldc = 512;  col0 = bn - 2048; doWF = true; }
        else if (bn < 3072) { Cf = F2; ldc = 512;  col0 = bn - 2560; doWF = true; }
        else                { Sh = H0; ldcs = 384; col0 = bn - 3072; doSH = true; }
    } else if constexpr (MODE == 2) {
        if (bn < 2048)      { Cf = F0; ldc = 2048; col0 = bn;        doAcc = true; doWF = true; }
        else if (bn < 2560) { Cf = F1; ldc = 512;  col0 = bn - 2048; doAcc = true; doWF = true; }
        else { Cf = F2; ldc = 512; col0 = bn - 2560; doAcc = true;
               Sh = H0; ldcs = 512; doSH = true; }
    } else if constexpr (MODE == 3) {
        if (bn < 2048)      { Cf = F0; ldc = 2048; col0 = bn;        doWF = true; }
        else                { Sh = H0; ldcs = 128; col0 = bn - 2048; doSH = true; }
    } else {
        Cf = F0; ldc = 2048; col0 = bn; doAcc = true; doWF = true;
    }

#pragma unroll
    for (int mt = 0; mt < MT; mt++) {
#pragma unroll
        for (int nt = 0; nt < NT; nt++) {
            int r0 = bm + wm0 + mt*16 + crow;
            int c0 = col0 + wn0 + nt*8 + ccol;
            float v00 = acc[mt][nt][0], v01 = acc[mt][nt][1];
            float v10 = acc[mt][nt][2], v11 = acc[mt][nt][3];
            if (doAcc) {
                float2 o0 = *(float2*)&Cf[(size_t)r0 * ldc + c0];
                float2 o1 = *(float2*)&Cf[(size_t)(r0+8) * ldc + c0];
                v00 += o0.x; v01 += o0.y; v10 += o1.x; v11 += o1.y;
            }
            if (doWF) {
                *(float2*)&Cf[(size_t)r0 * ldc + c0]     = make_float2(v00, v01);
                *(float2*)&Cf[(size_t)(r0+8) * ldc + c0] = make_float2(v10, v11);
            }
            if (doSH) {
                *(uint32_t*)&Sh[(size_t)r0 * ldcs + c0]     = packh2(v00, v01);
                *(uint32_t*)&Sh[(size_t)(r0+8) * ldcs + c0] = packh2(v10, v11);
            }
        }
    }
}

// ============================================================
// Tensor-core flash attention — single-pass fp16 (R12 best).
// ============================================================
static constexpr int AQ_H = 0;          // Q: 128*136 halves
static constexpr int ASTG = 17408;      // halves per stage (K + V)
static constexpr int AVH = 8704;
static constexpr int ATTN_SMEM_BYTES = (17408 + 2 * ASTG) * 2;  // 104448

__global__ void __launch_bounds__(256, 2) attn_mma_kernel(
    const __half* __restrict__ qh,
    const __half* __restrict__ kh,
    const __half* __restrict__ vh,
    __half* __restrict__ aoh)
{
    extern __shared__ char dynsm[];
    __half* sm = (__half*)dynsm;
    const int qb = blockIdx.x, h = blockIdx.y, b = blockIdx.z;
    const int i0 = qb * 128;
    const int tid = threadIdx.x, lane = tid & 31, warp = tid >> 5;
    const int kvh = h >> 2;
    const uint32_t su = smem_u32(sm);

#pragma unroll
    for (int c = tid; c < 128 * 16; c += 256) {
        int r = c >> 4, sg = c & 15;
        size_t g = ((size_t)(b*S + i0 + r)) * (H*HD) + h*HD + sg*8;
        *(uint4*)&sm[AQ_H + r*136 + sg*8] = *(const uint4*)(qh + g);
    }

    float O[16][4];
#pragma unroll
    for (int i = 0; i < 16; i++)
#pragma unroll
        for (int t = 0; t < 4; t++) O[i][t] = 0.f;
    float m0 = -1e30f, m1 = -1e30f, l0 = 0.f, l1 = 0.f;

    const int rowA = ((lane >> 3) & 1) * 8 + (lane & 7);
    const int kselA = (lane >> 4) * 8;
    const int rowB = ((lane >> 4) & 1) * 8 + (lane & 7);
    const int kselB = ((lane >> 3) & 1) * 8;
    const int rowV = ((lane >> 3) & 1) * 8 + (lane & 7);
    const int colV = (lane >> 4) * 8;

    int startb = 2*qb - 8; if (startb < 1) startb = 1;
    const int kb_end = 2*qb + 1;
    const int nblk = 1 + (kb_end - startb + 1);

    const int ir0 = i0 + warp*16 + (lane >> 2);
    const int ir1 = ir0 + 8;

    auto kbof = [&](int i) { return (i == 0) ? 0 : (startb + i - 1); };
    auto load_kv = [&](int st, int kb) {
        uint32_t base = su + (uint32_t)(17408 + ASTG * st) * 2;
#pragma unroll
        for (int c = tid; c < 64 * 16; c += 256) {
            int r = c >> 4, sg = c & 15;
            size_t g = ((size_t)(b*S + kb*64 + r)) * (KVH*HD) + kvh*HD + sg*8;
            uint32_t so = (uint32_t)(r*136 + sg*8) * 2;
            CP16(base + so, kh + g);
            CP16(base + AVH*2 + so, vh + g);
        }
    };

    load_kv(0, kbof(0));
    CP_COMMIT();
    if (nblk > 1) { load_kv(1, kbof(1)); CP_COMMIT(); }

    for (int bi = 0; bi < nblk; bi++) {
        if (bi + 1 < nblk) CP_WAIT1(); else CP_WAIT0();
        __syncthreads();
        const int kb = kbof(bi);
        const uint32_t sb2 = su + (uint32_t)(17408 + ASTG * (bi & 1)) * 2;

        float sc[8][4];
#pragma unroll
        for (int i = 0; i < 8; i++)
#pragma unroll
            for (int t = 0; t < 4; t++) sc[i][t] = 0.f;

#pragma unroll
        for (int kk = 0; kk < 8; kk++) {
            uint32_t ah[4];
            uint32_t offA = (uint32_t)((warp*16 + rowA)*136 + kk*16 + kselA) * 2;
            ldm_x4(ah, su + AQ_H*2 + offA);
#pragma unroll
            for (int g2 = 0; g2 < 4; g2++) {
                uint32_t bh4[4];
                uint32_t offB = (uint32_t)((g2*16 + rowB)*136 + kk*16 + kselB) * 2;
                ldm_x4(bh4, sb2 + offB);
                mma16816(sc[2*g2],   ah, bh4);
                mma16816(sc[2*g2+1], ah, bh4 + 2);
            }
        }

        const int jb = kb*64 + (lane & 3) * 2;
        float mx0 = -1e30f, mx1 = -1e30f;
#pragma unroll
        for (int nt = 0; nt < 8; nt++) {
            int j0 = jb + nt*8, j1 = j0 + 1;
            if (!((j0 <= ir0) && (((ir0 - j0) < WINDOW) || (j0 < GLOBALK)))) sc[nt][0] = -1e30f;
            if (!((j1 <= ir0) && (((ir0 - j1) < WINDOW) || (j1 < GLOBALK)))) sc[nt][1] = -1e30f;
            if (!((j0 <= ir1) && (((ir1 - j0) < WINDOW) || (j0 < GLOBALK)))) sc[nt][2] = -1e30f;
            if (!((j1 <= ir1) && (((ir1 - j1) < WINDOW) || (j1 < GLOBALK)))) sc[nt][3] = -1e30f;
            mx0 = fmaxf(mx0, fmaxf(sc[nt][0], sc[nt][1]));
            mx1 = fmaxf(mx1, fmaxf(sc[nt][2], sc[nt][3]));
        }
        mx0 = fmaxf(mx0, __shfl_xor_sync(0xffffffffu, mx0, 1));
        mx0 = fmaxf(mx0, __shfl_xor_sync(0xffffffffu, mx0, 2));
        mx1 = fmaxf(mx1, __shfl_xor_sync(0xffffffffu, mx1, 1));
        mx1 = fmaxf(mx1, __shfl_xor_sync(0xffffffffu, mx1, 2));

        float nm0 = fmaxf(m0, mx0), nm1 = fmaxf(m1, mx1);
        float a0 = __expf(m0 - nm0), a1 = __expf(m1 - nm1);
        float s0 = 0.f, s1 = 0.f;
#pragma unroll
        for (int nt = 0; nt < 8; nt++) {
            sc[nt][0] = __expf(sc[nt][0] - nm0);
            sc[nt][1] = __expf(sc[nt][1] - nm0);
            sc[nt][2] = __expf(sc[nt][2] - nm1);
            sc[nt][3] = __expf(sc[nt][3] - nm1);
            s0 += sc[nt][0] + sc[nt][1];
            s1 += sc[nt][2] + sc[nt][3];
        }
        s0 += __shfl_xor_sync(0xffffffffu, s0, 1);
        s0 += __shfl_xor_sync(0xffffffffu, s0, 2);
        s1 += __shfl_xor_sync(0xffffffffu, s1, 1);
        s1 += __shfl_xor_sync(0xffffffffu, s1, 2);
        l0 = l0 * a0 + s0;  l1 = l1 * a1 + s1;
        m0 = nm0;  m1 = nm1;
#pragma unroll
        for (int dt = 0; dt < 16; dt++) {
            O[dt][0] *= a0; O[dt][1] *= a0;
            O[dt][2] *= a1; O[dt][3] *= a1;
        }

#pragma unroll
        for (int kk = 0; kk < 4; kk++) {
            uint32_t pah[4];
            pah[0] = packh2(sc[2*kk][0],   sc[2*kk][1]);
            pah[1] = packh2(sc[2*kk][2],   sc[2*kk][3]);
            pah[2] = packh2(sc[2*kk+1][0], sc[2*kk+1][1]);
            pah[3] = packh2(sc[2*kk+1][2], sc[2*kk+1][3]);
#pragma unroll
            for (int dt2 = 0; dt2 < 8; dt2++) {
                uint32_t vbh[4];
                uint32_t offV = (uint32_t)((kk*16 + rowV)*136 + dt2*16 + colV) * 2;
                ldm_x4_t(vbh, sb2 + AVH*2 + offV);
                mma16816(O[2*dt2],   pah, vbh);
                mma16816(O[2*dt2+1], pah, vbh + 2);
            }
        }

        __syncthreads();
        if (bi + 2 < nblk) { load_kv(bi & 1, kbof(bi + 2)); CP_COMMIT(); }
    }

    const float inv0 = 1.f / l0, inv1 = 1.f / l1;
    const size_t rbase0 = ((size_t)(b*S + i0 + warp*16 + (lane >> 2))) * (H*HD);
    const size_t rbase1 = rbase0 + 8 * (size_t)(H*HD);
#pragma unroll
    for (int dt = 0; dt < 16; dt++) {
        int cc = h*HD + dt*8 + (lane & 3) * 2;
        *(uint32_t*)&aoh[rbase0 + cc] = packh2(O[dt][0]*inv0, O[dt][1]*inv0);
        *(uint32_t*)&aoh[rbase1 + cc] = packh2(O[dt][2]*inv1, O[dt][3]*inv1);
    }
}

// ============================================================
// Host side
// ============================================================
static constexpr int SMEM_GEMM = 2 * (128*40 + 2*128*40) * 2;   // 61440

extern "C" void kernel_launch(void* const* d_in, const int* in_sizes, int n_in,
                              void* d_out, int out_size)
{
    const float* x = (const float*)d_in[0];
    float* out = (float*)d_out;

    float *q, *k, *v;
    __half *xh, *wh, *wl, *th, *aoh, *qhp, *khp, *vhp;
    cudaGetSymbolAddress((void**)&q,   g_q);
    cudaGetSymbolAddress((void**)&k,   g_k);
    cudaGetSymbolAddress((void**)&v,   g_v);
    cudaGetSymbolAddress((void**)&xh,  g_xh);
    cudaGetSymbolAddress((void**)&wh,  g_wh);
    cudaGetSymbolAddress((void**)&wl,  g_wl);
    cudaGetSymbolAddress((void**)&th,  g_th);
    cudaGetSymbolAddress((void**)&aoh, g_aoh);
    cudaGetSymbolAddress((void**)&qhp, g_qh);
    cudaGetSymbolAddress((void**)&khp, g_kh);
    cudaGetSymbolAddress((void**)&vhp, g_vh);

    cudaFuncSetAttribute(gemm_mma<1>, cudaFuncAttributeMaxDynamicSharedMemorySize, SMEM_GEMM);
    cudaFuncSetAttribute(gemm_mma<2>, cudaFuncAttributeMaxDynamicSharedMemorySize, SMEM_GEMM);
    cudaFuncSetAttribute(gemm_mma<3>, cudaFuncAttributeMaxDynamicSharedMemorySize, SMEM_GEMM);
    cudaFuncSetAttribute(gemm_mma<4>, cudaFuncAttributeMaxDynamicSharedMemorySize, SMEM_GEMM);
    cudaFuncSetAttribute(attn_mma_kernel,
        cudaFuncAttributeMaxDynamicSharedMemorySize, ATTN_SMEM_BYTES);

    const int M = MROWS;

    // ---- converts ----
    cvtx_kernel<<<(M*D/4 + 255)/256, 256>>>(x, xh, M*D/4);
    cvtw_kernel<<<(3047424 + 255)/256, 256>>>(
        (const float*)d_in[1], (const float*)d_in[2], (const float*)d_in[3],
        (const float*)d_in[4], (const float*)d_in[5], (const float*)d_in[6],
        (const float*)d_in[7], (const float*)d_in[8], (const float*)d_in[9],
        (const float*)d_in[10], (const float*)d_in[11], (const float*)d_in[12],
        wh, wl);

    // ---- G1: q|k|v|th = x @ [wq_w; wk_w; wv_w; wq_a; wk_a; wv_a]^T ----
    gemm_mma<1><<<dim3(3456/128, 32), 128, SMEM_GEMM>>>(
        xh, D, wh+OFF_QKVW, wl+OFF_QKVW, D,
        q, k, v, th, M, 3456, D);

    // ---- G2: fused LoRA b-projections (v-range writes vh) ----
    gemm_mma<2><<<dim3(3072/128, 32), 128, SMEM_GEMM>>>(
        th, 384, wh+OFF_QB, wl+OFF_QB, 128,
        q, k, v, vhp, M, 3072, 128);

    // ---- RoPE + fp16 convert (hi only) ----
    {
        int tq = M * H * 64;
        rope_split_kernel<<<(tq + 255)/256, 256>>>(q, qhp, H, SCALE, tq);
        int tk = M * KVH * 64;
        rope_split_kernel<<<(tk + 255)/256, 256>>>(k, khp, KVH, 1.0f, tk);
    }

    // ---- attention (single-pass fp16) ----
    {
        dim3 grid(S/128, H, B);
        attn_mma_kernel<<<grid, 256, ATTN_SMEM_BYTES>>>(qhp, khp, vhp, aoh);
    }

    // ---- G3: out|th = ao @ [wo_w; wo_a]^T ----
    gemm_mma<3><<<dim3(2176/128, 32), 128, SMEM_GEMM>>>(
        aoh, 2048, wh+OFF_OW, wl+OFF_OW, 2048,
        out, nullptr, nullptr, th, M, 2176, 2048);

    // ---- G4: out += th @ wo_b^T ----
    gemm_mma<4><<<dim3(2048/128, 32), 128, SMEM_GEMM>>>(
        th, 128, wh+OFF_OB, wl+OFF_OB, 128,
        out, nullptr, nullptr, nullptr, M, 2048, 128);
}

// round 14
// speedup vs baseline: 1.0809x; 1.0809x over previous
#include <cuda_runtime.h>
#include <cuda_fp16.h>
#include <math.h>
#include <stdint.h>

// Problem constants
static constexpr int B = 2, S = 2048, D = 2048;
static constexpr int H = 16, KVH = 4, HD = 128;
static constexpr int MROWS = B * S;            // 4096
static constexpr int WINDOW = 512, GLOBALK = 64;
static constexpr float SCALE = 0.08838834764831845f;  // 1/sqrt(128)

// ------------- scratch (device globals) -------------
__device__ float g_q [(size_t)MROWS * (H * HD)];
__device__ float g_k [(size_t)MROWS * (KVH * HD)];
__device__ float g_v [(size_t)MROWS * (KVH * HD)];

__device__ __half g_xh[(size_t)MROWS * D];
__device__ __half g_wh[12189696];
__device__ __half g_wl[12189696];
__device__ __half g_th[(size_t)MROWS * 384];
__device__ __half g_aoh[(size_t)MROWS * (H * HD)];
__device__ __half g_qh[(size_t)MROWS * (H * HD)];
__device__ __half g_kh[(size_t)MROWS * (KVH * HD)];
__device__ __half g_vh[(size_t)MROWS * (KVH * HD)];

// weight pool layout (elements)
static constexpr size_t OFF_QKVW = 0;
static constexpr size_t OFF_QB   = 7077888;
static constexpr size_t OFF_OW   = 7471104;
static constexpr size_t OFF_OB   = 11927552;

// ============================================================
// helpers
// ============================================================
__device__ __forceinline__ uint32_t smem_u32(const void* p) {
    uint32_t a;
    asm("{ .reg .u64 t; cvta.to.shared.u64 t, %1; cvt.u32.u64 %0, t; }"
        : "=r"(a) : "l"(p));
    return a;
}
__device__ __forceinline__ void ldm_x4(uint32_t* r, uint32_t addr) {
    asm volatile("ldmatrix.sync.aligned.m8n8.x4.shared.b16 {%0,%1,%2,%3}, [%4];"
                 : "=r"(r[0]), "=r"(r[1]), "=r"(r[2]), "=r"(r[3]) : "r"(addr));
}
__device__ __forceinline__ void ldm_x4_t(uint32_t* r, uint32_t addr) {
    asm volatile("ldmatrix.sync.aligned.m8n8.x4.trans.shared.b16 {%0,%1,%2,%3}, [%4];"
                 : "=r"(r[0]), "=r"(r[1]), "=r"(r[2]), "=r"(r[3]) : "r"(addr));
}
__device__ __forceinline__ void mma16816(float* c, const uint32_t* a, const uint32_t* b) {
    asm volatile(
        "mma.sync.aligned.m16n8k16.row.col.f32.f16.f16.f32 "
        "{%0,%1,%2,%3}, {%4,%5,%6,%7}, {%8,%9}, {%0,%1,%2,%3};"
        : "+f"(c[0]), "+f"(c[1]), "+f"(c[2]), "+f"(c[3])
        : "r"(a[0]), "r"(a[1]), "r"(a[2]), "r"(a[3]), "r"(b[0]), "r"(b[1]));
}
#define CP16(saddr, gptr) \
    asm volatile("cp.async.cg.shared.global [%0], [%1], 16;" :: "r"(saddr), "l"(gptr))
#define CP_COMMIT() asm volatile("cp.async.commit_group;" ::: "memory")
#define CP_WAIT0()  asm volatile("cp.async.wait_group 0;" ::: "memory")
#define CP_WAIT1()  asm volatile("cp.async.wait_group 1;" ::: "memory")

__device__ __forceinline__ uint32_t packh2(float x, float y) {
    __half2 h = __floats2half2_rn(x, y);
    return *(uint32_t*)&h;
}
__device__ __forceinline__ void splith(float x, float y, uint32_t& h, uint32_t& l) {
    __half hx = __float2half_rn(x), hy = __float2half_rn(y);
    __half lx = __float2half_rn(x - __half2float(hx));
    __half ly = __float2half_rn(y - __half2float(hy));
    uint16_t uhx = *(uint16_t*)&hx, uhy = *(uint16_t*)&hy;
    uint16_t ulx = *(uint16_t*)&lx, uly = *(uint16_t*)&ly;
    h = (uint32_t)uhx | ((uint32_t)uhy << 16);
    l = (uint32_t)ulx | ((uint32_t)uly << 16);
}

// ============================================================
// converters
// ============================================================
__global__ void cvtx_kernel(const float* __restrict__ x,
                            __half* __restrict__ hi, int n4)
{
    int i = blockIdx.x * 256 + threadIdx.x;
    if (i >= n4) return;
    float4 v = ((const float4*)x)[i];
    __half h[4] = { __float2half_rn(v.x), __float2half_rn(v.y),
                    __float2half_rn(v.z), __float2half_rn(v.w) };
    *(uint2*)&hi[4*(size_t)i] = *(uint2*)h;
}

__global__ void cvtw_kernel(
    const float* p0, const float* p1, const float* p2, const float* p3,
    const float* p4, const float* p5, const float* p6, const float* p7,
    const float* p8, const float* p9, const float* p10, const float* p11,
    __half* __restrict__ hi, __half* __restrict__ lo)
{
    const float* srcs[12] = {p0,p1,p2,p3,p4,p5,p6,p7,p8,p9,p10,p11};
    const int pre[13] = {0, 1048576, 1114112, 1179648, 1441792, 1507328,
                         1523712, 1785856, 1851392, 1867776, 2916352,
                         2981888, 3047424};
    const int dst[12] = {0, 1572864, 1769472, 1048576, 1638400, 1835008,
                         1310720, 1703936, 1851392, 1867776, 2916352, 2981888};
    int gi = blockIdx.x * 256 + threadIdx.x;
    if (gi >= 3047424) return;
    int s = 0;
#pragma unroll
    for (int t = 1; t < 12; t++) if (gi >= pre[t]) s = t;
    int local = gi - pre[s];
    float4 v = ((const float4*)srcs[s])[local];
    uint32_t h01, l01, h23, l23;
    splith(v.x, v.y, h01, l01);
    splith(v.z, v.w, h23, l23);
    size_t o = 4 * ((size_t)dst[s] + local);
    *(uint32_t*)&hi[o]   = h01; *(uint32_t*)&hi[o+2] = h23;
    *(uint32_t*)&lo[o]   = l01; *(uint32_t*)&lo[o+2] = l23;
}

// ============================================================
// fused RoPE (+scale) + fp16 convert (hi only)
// ============================================================
__global__ void rope_split_kernel(const float* __restrict__ t,
                                  __half* __restrict__ hi,
                                  int heads, float scale, int total)
{
    int idx = blockIdx.x * 256 + threadIdx.x;
    if (idx >= total) return;
    int d   = idx & 63;
    int r   = idx >> 6;
    int s   = (r / heads) & (S - 1);
    double invf = pow(1.0e6, -(double)d / 64.0);
    float ang = (float)s * (float)invf;
    float sn, cs;
    sincosf(ang, &sn, &cs);
    const float* p = t + (size_t)r * 128 + 2 * d;
    float xr = p[0], xi = p[1];
    float o0 = (xr * cs - xi * sn) * scale;
    float o1 = (xr * sn + xi * cs) * scale;
    *(uint32_t*)&hi[(size_t)r * 128 + 2 * d] = packh2(o0, o1);
}

// ============================================================
// mma.sync GEMM (R12 best config): 128x64 CTA tile, 8 warps
// (4x2 of 32x32), K-chunk 64 (stride 72), 2-stage cp.async,
// register double-buffered fragments.
// TWOB: true = 2-pass B (hi+lo), false = single-pass (hi only).
// MODE 1 (QKVA) / 2 (BPROJ) / 3 (OUT) / 4 (ACC).
// ============================================================
template<int MODE, bool TWOB>
__global__ void __launch_bounds__(256, 2) gemm_mma(
    const __half* __restrict__ Ahi, const int lda,
    const __half* __restrict__ Bhi, const __half* __restrict__ Blo, const int ldb,
    float* __restrict__ F0, float* __restrict__ F1, float* __restrict__ F2,
    __half* __restrict__ H0,
    const int M, const int N, const int K)
{
    constexpr int BM = 128, BN = 64;
    constexpr int NTHR = 256, MT = 2, NT = 4;
    constexpr int ASZ = BM * 72, BSZ = BN * 72;  // halves
    constexpr int STG = ASZ + 2 * BSZ;
    extern __shared__ char dynsm[];
    __half* smem = (__half*)dynsm;

    const int tid = threadIdx.x, lane = tid & 31, warp = tid >> 5;
    const int bm = blockIdx.y * BM;
    const int bn = blockIdx.x * BN;
    const int wm0 = (warp >> 1) * 32, wn0 = (warp & 1) * 32;
    const uint32_t su = smem_u32(smem);

    const __half* Aptr = Ahi;
    if constexpr (MODE == 2)
        Aptr = Ahi + ((bn < 2048) ? 0 : (bn < 2560 ? 128 : 256));

    const int rowA = ((lane >> 3) & 1) * 8 + (lane & 7);
    const int kselA = (lane >> 4) * 8;
    const int rowB = ((lane >> 4) & 1) * 8 + (lane & 7);
    const int kselB = ((lane >> 3) & 1) * 8;

    float acc[MT][NT][4];
#pragma unroll
    for (int i = 0; i < MT; i++)
#pragma unroll
        for (int j = 0; j < NT; j++)
#pragma unroll
            for (int t = 0; t < 4; t++) acc[i][j][t] = 0.f;

    auto load_stage = [&](int st, int k0) {
        uint32_t base = su + (uint32_t)st * STG * 2;
#pragma unroll
        for (int c = tid; c < BM * 8; c += NTHR) {
            int r = c >> 3, sg = c & 7;
            uint32_t so = (uint32_t)(r * 144 + sg * 16);
            size_t ga = (size_t)(bm + r) * lda + k0 + sg * 8;
            CP16(base + so, Aptr + ga);
        }
#pragma unroll
        for (int c = tid; c < BN * 8; c += NTHR) {
            int r = c >> 3, sg = c & 7;
            uint32_t so = (uint32_t)(r * 144 + sg * 16);
            size_t gb = (size_t)(bn + r) * ldb + k0 + sg * 8;
            CP16(base + ASZ * 2 + so, Bhi + gb);
            if constexpr (TWOB)
                CP16(base + (ASZ + BSZ) * 2 + so, Blo + gb);
        }
    };

    uint32_t ah[2][MT][4], bh[2][NT][2], bl[2][NT][2];

    const int nk = K / 64;
    load_stage(0, 0);
    CP_COMMIT();

    for (int kt = 0; kt < nk; kt++) {
        const int buf = kt & 1;
        if (kt + 1 < nk) {
            load_stage((kt + 1) & 1, (kt + 1) * 64);
            CP_COMMIT();
            CP_WAIT1();
        } else {
            CP_WAIT0();
        }
        __syncthreads();

        const uint32_t uAh = su + (uint32_t)buf * STG * 2;
        const uint32_t uBh = uAh + ASZ * 2;
        const uint32_t uBl = uAh + (ASZ + BSZ) * 2;

        auto ldfrag = [&](int kk, int pb) {
#pragma unroll
            for (int mt = 0; mt < MT; mt++) {
                uint32_t off = (uint32_t)((wm0 + mt*16 + rowA) * 72 + kk*16 + kselA) * 2;
                ldm_x4(ah[pb][mt], uAh + off);
            }
#pragma unroll
            for (int g = 0; g < 2; g++) {
                uint32_t off = (uint32_t)((wn0 + g*16 + rowB) * 72 + kk*16 + kselB) * 2;
                uint32_t r4[4];
                ldm_x4(r4, uBh + off);
                bh[pb][2*g][0] = r4[0]; bh[pb][2*g][1] = r4[1];
                bh[pb][2*g+1][0] = r4[2]; bh[pb][2*g+1][1] = r4[3];
                if constexpr (TWOB) {
                    ldm_x4(r4, uBl + off);
                    bl[pb][2*g][0] = r4[0]; bl[pb][2*g][1] = r4[1];
                    bl[pb][2*g+1][0] = r4[2]; bl[pb][2*g+1][1] = r4[3];
                }
            }
        };

        ldfrag(0, 0);
#pragma unroll
        for (int kk = 0; kk < 4; kk++) {
            const int pb = kk & 1;
            if (kk < 3) ldfrag(kk + 1, (kk + 1) & 1);
#pragma unroll
            for (int mt = 0; mt < MT; mt++)
#pragma unroll
                for (int nt = 0; nt < NT; nt++)
                    mma16816(acc[mt][nt], ah[pb][mt], bh[pb][nt]);
            if constexpr (TWOB) {
#pragma unroll
                for (int mt = 0; mt < MT; mt++)
#pragma unroll
                    for (int nt = 0; nt < NT; nt++)
                        mma16816(acc[mt][nt], ah[pb][mt], bl[pb][nt]);
            }
        }
        __syncthreads();
    }

    // ---- epilogue: CTA-uniform routing ----
    const int crow = lane >> 2, ccol = (lane & 3) * 2;
    float* Cf = nullptr;  __half *Sh = nullptr;
    int ldc = 0, ldcs = 0, col0 = bn;
    bool doAcc = false, doWF = false, doSH = false;

    if constexpr (MODE == 1) {
        if (bn < 2048)      { Cf = F0; ldc = 2048; col0 = bn;        doWF = true; }
        else if (bn < 2560) { Cf = F1; ldc = 512;  col0 = bn - 2048; doWF = true; }
        else if (bn < 3072) { Cf = F2; ldc = 512;  col0 = bn - 2560; doWF = true; }
        else                { Sh = H0; ldcs = 384; col0 = bn - 3072; doSH = true; }
    } else if constexpr (MODE == 2) {
        if (bn < 2048)      { Cf = F0; ldc = 2048; col0 = bn;        doAcc = true; doWF = true; }
        else if (bn < 2560) { Cf = F1; ldc = 512;  col0 = bn - 2048; doAcc = true; doWF = true; }
        else { Cf = F2; ldc = 512; col0 = bn - 2560; doAcc = true;
               Sh = H0; ldcs = 512; doSH = true; }
    } else if constexpr (MODE == 3) {
        if (bn < 2048)      { Cf = F0; ldc = 2048; col0 = bn;        doWF = true; }
        else                { Sh = H0; ldcs = 128; col0 = bn - 2048; doSH = true; }
    } else {
        Cf = F0; ldc = 2048; col0 = bn; doAcc = true; doWF = true;
    }

#pragma unroll
    for (int mt = 0; mt < MT; mt++) {
#pragma unroll
        for (int nt = 0; nt < NT; nt++) {
            int r0 = bm + wm0 + mt*16 + crow;
            int c0 = col0 + wn0 + nt*8 + ccol;
            float v00 = acc[mt][nt][0], v01 = acc[mt][nt][1];
            float v10 = acc[mt][nt][2], v11 = acc[mt][nt][3];
            if (doAcc) {
                float2 o0 = *(float2*)&Cf[(size_t)r0 * ldc + c0];
                float2 o1 = *(float2*)&Cf[(size_t)(r0+8) * ldc + c0];
                v00 += o0.x; v01 += o0.y; v10 += o1.x; v11 += o1.y;
            }
            if (doWF) {
                *(float2*)&Cf[(size_t)r0 * ldc + c0]     = make_float2(v00, v01);
                *(float2*)&Cf[(size_t)(r0+8) * ldc + c0] = make_float2(v10, v11);
            }
            if (doSH) {
                *(uint32_t*)&Sh[(size_t)r0 * ldcs + c0]     = packh2(v00, v01);
                *(uint32_t*)&Sh[(size_t)(r0+8) * ldcs + c0] = packh2(v10, v11);
            }
        }
    }
}

// ============================================================
// Tensor-core flash attention — single-pass fp16 (R12 best).
// ============================================================
static constexpr int AQ_H = 0;
static constexpr int ASTG = 17408;
static constexpr int AVH = 8704;
static constexpr int ATTN_SMEM_BYTES = (17408 + 2 * ASTG) * 2;  // 104448

__global__ void __launch_bounds__(256, 2) attn_mma_kernel(
    const __half* __restrict__ qh,
    const __half* __restrict__ kh,
    const __half* __restrict__ vh,
    __half* __restrict__ aoh)
{
    extern __shared__ char dynsm[];
    __half* sm = (__half*)dynsm;
    const int qb = blockIdx.x, h = blockIdx.y, b = blockIdx.z;
    const int i0 = qb * 128;
    const int tid = threadIdx.x, lane = tid & 31, warp = tid >> 5;
    const int kvh = h >> 2;
    const uint32_t su = smem_u32(sm);

#pragma unroll
    for (int c = tid; c < 128 * 16; c += 256) {
        int r = c >> 4, sg = c & 15;
        size_t g = ((size_t)(b*S + i0 + r)) * (H*HD) + h*HD + sg*8;
        *(uint4*)&sm[AQ_H + r*136 + sg*8] = *(const uint4*)(qh + g);
    }

    float O[16][4];
#pragma unroll
    for (int i = 0; i < 16; i++)
#pragma unroll
        for (int t = 0; t < 4; t++) O[i][t] = 0.f;
    float m0 = -1e30f, m1 = -1e30f, l0 = 0.f, l1 = 0.f;

    const int rowA = ((lane >> 3) & 1) * 8 + (lane & 7);
    const int kselA = (lane >> 4) * 8;
    const int rowB = ((lane >> 4) & 1) * 8 + (lane & 7);
    const int kselB = ((lane >> 3) & 1) * 8;
    const int rowV = ((lane >> 3) & 1) * 8 + (lane & 7);
    const int colV = (lane >> 4) * 8;

    int startb = 2*qb - 8; if (startb < 1) startb = 1;
    const int kb_end = 2*qb + 1;
    const int nblk = 1 + (kb_end - startb + 1);

    const int ir0 = i0 + warp*16 + (lane >> 2);
    const int ir1 = ir0 + 8;

    auto kbof = [&](int i) { return (i == 0) ? 0 : (startb + i - 1); };
    auto load_kv = [&](int st, int kb) {
        uint32_t base = su + (uint32_t)(17408 + ASTG * st) * 2;
#pragma unroll
        for (int c = tid; c < 64 * 16; c += 256) {
            int r = c >> 4, sg = c & 15;
            size_t g = ((size_t)(b*S + kb*64 + r)) * (KVH*HD) + kvh*HD + sg*8;
            uint32_t so = (uint32_t)(r*136 + sg*8) * 2;
            CP16(base + so, kh + g);
            CP16(base + AVH*2 + so, vh + g);
        }
    };

    load_kv(0, kbof(0));
    CP_COMMIT();
    if (nblk > 1) { load_kv(1, kbof(1)); CP_COMMIT(); }

    for (int bi = 0; bi < nblk; bi++) {
        if (bi + 1 < nblk) CP_WAIT1(); else CP_WAIT0();
        __syncthreads();
        const int kb = kbof(bi);
        const uint32_t sb2 = su + (uint32_t)(17408 + ASTG * (bi & 1)) * 2;

        float sc[8][4];
#pragma unroll
        for (int i = 0; i < 8; i++)
#pragma unroll
            for (int t = 0; t < 4; t++) sc[i][t] = 0.f;

#pragma unroll
        for (int kk = 0; kk < 8; kk++) {
            uint32_t ah[4];
            uint32_t offA = (uint32_t)((warp*16 + rowA)*136 + kk*16 + kselA) * 2;
            ldm_x4(ah, su + AQ_H*2 + offA);
#pragma unroll
            for (int g2 = 0; g2 < 4; g2++) {
                uint32_t bh4[4];
                uint32_t offB = (uint32_t)((g2*16 + rowB)*136 + kk*16 + kselB) * 2;
                ldm_x4(bh4, sb2 + offB);
                mma16816(sc[2*g2],   ah, bh4);
                mma16816(sc[2*g2+1], ah, bh4 + 2);
            }
        }

        const int jb = kb*64 + (lane & 3) * 2;
        float mx0 = -1e30f, mx1 = -1e30f;
#pragma unroll
        for (int nt = 0; nt < 8; nt++) {
            int j0 = jb + nt*8, j1 = j0 + 1;
            if (!((j0 <= ir0) && (((ir0 - j0) < WINDOW) || (j0 < GLOBALK)))) sc[nt][0] = -1e30f;
            if (!((j1 <= ir0) && (((ir0 - j1) < WINDOW) || (j1 < GLOBALK)))) sc[nt][1] = -1e30f;
            if (!((j0 <= ir1) && (((ir1 - j0) < WINDOW) || (j0 < GLOBALK)))) sc[nt][2] = -1e30f;
            if (!((j1 <= ir1) && (((ir1 - j1) < WINDOW) || (j1 < GLOBALK)))) sc[nt][3] = -1e30f;
            mx0 = fmaxf(mx0, fmaxf(sc[nt][0], sc[nt][1]));
            mx1 = fmaxf(mx1, fmaxf(sc[nt][2], sc[nt][3]));
        }
        mx0 = fmaxf(mx0, __shfl_xor_sync(0xffffffffu, mx0, 1));
        mx0 = fmaxf(mx0, __shfl_xor_sync(0xffffffffu, mx0, 2));
        mx1 = fmaxf(mx1, __shfl_xor_sync(0xffffffffu, mx1, 1));
        mx1 = fmaxf(mx1, __shfl_xor_sync(0xffffffffu, mx1, 2));

        float nm0 = fmaxf(m0, mx0), nm1 = fmaxf(m1, mx1);
        float a0 = __expf(m0 - nm0), a1 = __expf(m1 - nm1);
        float s0 = 0.f, s1 = 0.f;
#pragma unroll
        for (int nt = 0; nt < 8; nt++) {
            sc[nt][0] = __expf(sc[nt][0] - nm0);
            sc[nt][1] = __expf(sc[nt][1] - nm0);
            sc[nt][2] = __expf(sc[nt][2] - nm1);
            sc[nt][3] = __expf(sc[nt][3] - nm1);
            s0 += sc[nt][0] + sc[nt][1];
            s1 += sc[nt][2] + sc[nt][3];
        }
        s0 += __shfl_xor_sync(0xffffffffu, s0, 1);
        s0 += __shfl_xor_sync(0xffffffffu, s0, 2);
        s1 += __shfl_xor_sync(0xffffffffu, s1, 1);
        s1 += __shfl_xor_sync(0xffffffffu, s1, 2);
        l0 = l0 * a0 + s0;  l1 = l1 * a1 + s1;
        m0 = nm0;  m1 = nm1;
#pragma unroll
        for (int dt = 0; dt < 16; dt++) {
            O[dt][0] *= a0; O[dt][1] *= a0;
            O[dt][2] *= a1; O[dt][3] *= a1;
        }

#pragma unroll
        for (int kk = 0; kk < 4; kk++) {
            uint32_t pah[4];
            pah[0] = packh2(sc[2*kk][0],   sc[2*kk][1]);
            pah[1] = packh2(sc[2*kk][2],   sc[2*kk][3]);
            pah[2] = packh2(sc[2*kk+1][0], sc[2*kk+1][1]);
            pah[3] = packh2(sc[2*kk+1][2], sc[2*kk+1][3]);
#pragma unroll
            for (int dt2 = 0; dt2 < 8; dt2++) {
                uint32_t vbh[4];
                uint32_t offV = (uint32_t)((kk*16 + rowV)*136 + dt2*16 + colV) * 2;
                ldm_x4_t(vbh, sb2 + AVH*2 + offV);
                mma16816(O[2*dt2],   pah, vbh);
                mma16816(O[2*dt2+1], pah, vbh + 2);
            }
        }

        __syncthreads();
        if (bi + 2 < nblk) { load_kv(bi & 1, kbof(bi + 2)); CP_COMMIT(); }
    }

    const float inv0 = 1.f / l0, inv1 = 1.f / l1;
    const size_t rbase0 = ((size_t)(b*S + i0 + warp*16 + (lane >> 2))) * (H*HD);
    const size_t rbase1 = rbase0 + 8 * (size_t)(H*HD);
#pragma unroll
    for (int dt = 0; dt < 16; dt++) {
        int cc = h*HD + dt*8 + (lane & 3) * 2;
        *(uint32_t*)&aoh[rbase0 + cc] = packh2(O[dt][0]*inv0, O[dt][1]*inv0);
        *(uint32_t*)&aoh[rbase1 + cc] = packh2(O[dt][2]*inv1, O[dt][3]*inv1);
    }
}

// ============================================================
// Host side
// ============================================================
static constexpr int SMEM_GEMM = 2 * (128*72 + 2*64*72) * 2;   // 73728

extern "C" void kernel_launch(void* const* d_in, const int* in_sizes, int n_in,
                              void* d_out, int out_size)
{
    const float* x = (const float*)d_in[0];
    float* out = (float*)d_out;

    float *q, *k, *v;
    __half *xh, *wh, *wl, *th, *aoh, *qhp, *khp, *vhp;
    cudaGetSymbolAddress((void**)&q,   g_q);
    cudaGetSymbolAddress((void**)&k,   g_k);
    cudaGetSymbolAddress((void**)&v,   g_v);
    cudaGetSymbolAddress((void**)&xh,  g_xh);
    cudaGetSymbolAddress((void**)&wh,  g_wh);
    cudaGetSymbolAddress((void**)&wl,  g_wl);
    cudaGetSymbolAddress((void**)&th,  g_th);
    cudaGetSymbolAddress((void**)&aoh, g_aoh);
    cudaGetSymbolAddress((void**)&qhp, g_qh);
    cudaGetSymbolAddress((void**)&khp, g_kh);
    cudaGetSymbolAddress((void**)&vhp, g_vh);

    auto G1 = gemm_mma<1, false>;   // QKV+A: single-pass B
    auto G2 = gemm_mma<2, true>;
    auto G3 = gemm_mma<3, true>;
    auto G4 = gemm_mma<4, true>;

    cudaFuncSetAttribute(G1, cudaFuncAttributeMaxDynamicSharedMemorySize, SMEM_GEMM);
    cudaFuncSetAttribute(G2, cudaFuncAttributeMaxDynamicSharedMemorySize, SMEM_GEMM);
    cudaFuncSetAttribute(G3, cudaFuncAttributeMaxDynamicSharedMemorySize, SMEM_GEMM);
    cudaFuncSetAttribute(G4, cudaFuncAttributeMaxDynamicSharedMemorySize, SMEM_GEMM);
    cudaFuncSetAttribute(attn_mma_kernel,
        cudaFuncAttributeMaxDynamicSharedMemorySize, ATTN_SMEM_BYTES);

    const int M = MROWS;

    // ---- converts ----
    cvtx_kernel<<<(M*D/4 + 255)/256, 256>>>(x, xh, M*D/4);
    cvtw_kernel<<<(3047424 + 255)/256, 256>>>(
        (const float*)d_in[1], (const float*)d_in[2], (const float*)d_in[3],
        (const float*)d_in[4], (const float*)d_in[5], (const float*)d_in[6],
        (const float*)d_in[7], (const float*)d_in[8], (const float*)d_in[9],
        (const float*)d_in[10], (const float*)d_in[11], (const float*)d_in[12],
        wh, wl);

    // ---- G1: q|k|v|th = x @ [wq_w; wk_w; wv_w; wq_a; wk_a; wv_a]^T ----
    G1<<<dim3(3456/64, 32), 256, SMEM_GEMM>>>(
        xh, D, wh+OFF_QKVW, wl+OFF_QKVW, D,
        q, k, v, th, M, 3456, D);

    // ---- G2: fused LoRA b-projections (v-range writes vh) ----
    G2<<<dim3(3072/64, 32), 256, SMEM_GEMM>>>(
        th, 384, wh+OFF_QB, wl+OFF_QB, 128,
        q, k, v, vhp, M, 3072, 128);

    // ---- RoPE + fp16 convert (hi only) ----
    {
        int tq = M * H * 64;
        rope_split_kernel<<<(tq + 255)/256, 256>>>(q, qhp, H, SCALE, tq);
        int tk = M * KVH * 64;
        rope_split_kernel<<<(tk + 255)/256, 256>>>(k, khp, KVH, 1.0f, tk);
    }

    // ---- attention (single-pass fp16) ----
    {
        dim3 grid(S/128, H, B);
        attn_mma_kernel<<<grid, 256, ATTN_SMEM_BYTES>>>(qhp, khp, vhp, aoh);
    }

    // ---- G3: out|th = ao @ [wo_w; wo_a]^T ----
    G3<<<dim3(2176/64, 32), 256, SMEM_GEMM>>>(
        aoh, 2048, wh+OFF_OW, wl+OFF_OW, 2048,
        out, nullptr, nullptr, th, M, 2176, 2048);

    // ---- G4: out += th @ wo_b^T ----
    G4<<<dim3(2048/64, 32), 256, SMEM_GEMM>>>(
        th, 128, wh+OFF_OB, wl+OFF_OB, 128,
        out, nullptr, nullptr, nullptr, M, 2048, 128);
}

// round 15
// speedup vs baseline: 1.1466x; 1.0608x over previous
#include <cuda_runtime.h>
#include <cuda_fp16.h>
#include <math.h>
#include <stdint.h>

// Problem constants
static constexpr int B = 2, S = 2048, D = 2048;
static constexpr int H = 16, KVH = 4, HD = 128;
static constexpr int MROWS = B * S;            // 4096
static constexpr int WINDOW = 512, GLOBALK = 64;
static constexpr float SCALE = 0.08838834764831845f;  // 1/sqrt(128)

// ------------- scratch (device globals) -------------
__device__ float g_q [(size_t)MROWS * (H * HD)];
__device__ float g_k [(size_t)MROWS * (KVH * HD)];
__device__ float g_v [(size_t)MROWS * (KVH * HD)];

__device__ __half g_xh[(size_t)MROWS * D];
__device__ __half g_wh[12189696];
__device__ __half g_th[(size_t)MROWS * 384];
__device__ __half g_aoh[(size_t)MROWS * (H * HD)];
__device__ __half g_qh[(size_t)MROWS * (H * HD)];
__device__ __half g_kh[(size_t)MROWS * (KVH * HD)];
__device__ __half g_vh[(size_t)MROWS * (KVH * HD)];

// weight pool layout (elements)
static constexpr size_t OFF_QKVW = 0;
static constexpr size_t OFF_QB   = 7077888;
static constexpr size_t OFF_OW   = 7471104;
static constexpr size_t OFF_OB   = 11927552;

// ============================================================
// helpers
// ============================================================
__device__ __forceinline__ uint32_t smem_u32(const void* p) {
    uint32_t a;
    asm("{ .reg .u64 t; cvta.to.shared.u64 t, %1; cvt.u32.u64 %0, t; }"
        : "=r"(a) : "l"(p));
    return a;
}
__device__ __forceinline__ void ldm_x4(uint32_t* r, uint32_t addr) {
    asm volatile("ldmatrix.sync.aligned.m8n8.x4.shared.b16 {%0,%1,%2,%3}, [%4];"
                 : "=r"(r[0]), "=r"(r[1]), "=r"(r[2]), "=r"(r[3]) : "r"(addr));
}
__device__ __forceinline__ void ldm_x4_t(uint32_t* r, uint32_t addr) {
    asm volatile("ldmatrix.sync.aligned.m8n8.x4.trans.shared.b16 {%0,%1,%2,%3}, [%4];"
                 : "=r"(r[0]), "=r"(r[1]), "=r"(r[2]), "=r"(r[3]) : "r"(addr));
}
__device__ __forceinline__ void mma16816(float* c, const uint32_t* a, const uint32_t* b) {
    asm volatile(
        "mma.sync.aligned.m16n8k16.row.col.f32.f16.f16.f32 "
        "{%0,%1,%2,%3}, {%4,%5,%6,%7}, {%8,%9}, {%0,%1,%2,%3};"
        : "+f"(c[0]), "+f"(c[1]), "+f"(c[2]), "+f"(c[3])
        : "r"(a[0]), "r"(a[1]), "r"(a[2]), "r"(a[3]), "r"(b[0]), "r"(b[1]));
}
#define CP16(saddr, gptr) \
    asm volatile("cp.async.cg.shared.global [%0], [%1], 16;" :: "r"(saddr), "l"(gptr))
#define CP_COMMIT() asm volatile("cp.async.commit_group;" ::: "memory")
#define CP_WAIT0()  asm volatile("cp.async.wait_group 0;" ::: "memory")
#define CP_WAIT1()  asm volatile("cp.async.wait_group 1;" ::: "memory")

__device__ __forceinline__ uint32_t packh2(float x, float y) {
    __half2 h = __floats2half2_rn(x, y);
    return *(uint32_t*)&h;
}

// ============================================================
// converters (hi only now)
// ============================================================
__global__ void cvtx_kernel(const float* __restrict__ x,
                            __half* __restrict__ hi, int n4)
{
    int i = blockIdx.x * 256 + threadIdx.x;
    if (i >= n4) return;
    float4 v = ((const float4*)x)[i];
    __half h[4] = { __float2half_rn(v.x), __float2half_rn(v.y),
                    __float2half_rn(v.z), __float2half_rn(v.w) };
    *(uint2*)&hi[4*(size_t)i] = *(uint2*)h;
}

__global__ void cvtw_kernel(
    const float* p0, const float* p1, const float* p2, const float* p3,
    const float* p4, const float* p5, const float* p6, const float* p7,
    const float* p8, const float* p9, const float* p10, const float* p11,
    __half* __restrict__ hi)
{
    const float* srcs[12] = {p0,p1,p2,p3,p4,p5,p6,p7,p8,p9,p10,p11};
    const int pre[13] = {0, 1048576, 1114112, 1179648, 1441792, 1507328,
                         1523712, 1785856, 1851392, 1867776, 2916352,
                         2981888, 3047424};
    const int dst[12] = {0, 1572864, 1769472, 1048576, 1638400, 1835008,
                         1310720, 1703936, 1851392, 1867776, 2916352, 2981888};
    int gi = blockIdx.x * 256 + threadIdx.x;
    if (gi >= 3047424) return;
    int s = 0;
#pragma unroll
    for (int t = 1; t < 12; t++) if (gi >= pre[t]) s = t;
    int local = gi - pre[s];
    float4 v = ((const float4*)srcs[s])[local];
    __half h[4] = { __float2half_rn(v.x), __float2half_rn(v.y),
                    __float2half_rn(v.z), __float2half_rn(v.w) };
    size_t o = 4 * ((size_t)dst[s] + local);
    *(uint2*)&hi[o] = *(uint2*)h;
}

// ============================================================
// fused RoPE (+scale) + fp16 convert (hi only)
// ============================================================
__global__ void rope_split_kernel(const float* __restrict__ t,
                                  __half* __restrict__ hi,
                                  int heads, float scale, int total)
{
    int idx = blockIdx.x * 256 + threadIdx.x;
    if (idx >= total) return;
    int d   = idx & 63;
    int r   = idx >> 6;
    int s   = (r / heads) & (S - 1);
    double invf = pow(1.0e6, -(double)d / 64.0);
    float ang = (float)s * (float)invf;
    float sn, cs;
    sincosf(ang, &sn, &cs);
    const float* p = t + (size_t)r * 128 + 2 * d;
    float xr = p[0], xi = p[1];
    float o0 = (xr * cs - xi * sn) * scale;
    float o1 = (xr * sn + xi * cs) * scale;
    *(uint32_t*)&hi[(size_t)r * 128 + 2 * d] = packh2(o0, o1);
}

// ============================================================
// mma.sync GEMM (R12/R14 best config): 128x64 CTA tile, 8 warps
// (4x2 of 32x32), K-chunk 64 (stride 72), 2-stage cp.async,
// register double-buffered fragments. Single-pass B (TWOB kept
// as a template knob for revertibility).
// MODE 1 (QKVA) / 2 (BPROJ) / 3 (OUT) / 4 (ACC).
// ============================================================
template<int MODE, bool TWOB>
__global__ void __launch_bounds__(256, 2) gemm_mma(
    const __half* __restrict__ Ahi, const int lda,
    const __half* __restrict__ Bhi, const __half* __restrict__ Blo, const int ldb,
    float* __restrict__ F0, float* __restrict__ F1, float* __restrict__ F2,
    __half* __restrict__ H0,
    const int M, const int N, const int K)
{
    constexpr int BM = 128, BN = 64;
    constexpr int NTHR = 256, MT = 2, NT = 4;
    constexpr int ASZ = BM * 72, BSZ = BN * 72;  // halves
    constexpr int STG = ASZ + (TWOB ? 2 : 1) * BSZ;
    extern __shared__ char dynsm[];
    __half* smem = (__half*)dynsm;

    const int tid = threadIdx.x, lane = tid & 31, warp = tid >> 5;
    const int bm = blockIdx.y * BM;
    const int bn = blockIdx.x * BN;
    const int wm0 = (warp >> 1) * 32, wn0 = (warp & 1) * 32;
    const uint32_t su = smem_u32(smem);

    const __half* Aptr = Ahi;
    if constexpr (MODE == 2)
        Aptr = Ahi + ((bn < 2048) ? 0 : (bn < 2560 ? 128 : 256));

    const int rowA = ((lane >> 3) & 1) * 8 + (lane & 7);
    const int kselA = (lane >> 4) * 8;
    const int rowB = ((lane >> 4) & 1) * 8 + (lane & 7);
    const int kselB = ((lane >> 3) & 1) * 8;

    float acc[MT][NT][4];
#pragma unroll
    for (int i = 0; i < MT; i++)
#pragma unroll
        for (int j = 0; j < NT; j++)
#pragma unroll
            for (int t = 0; t < 4; t++) acc[i][j][t] = 0.f;

    auto load_stage = [&](int st, int k0) {
        uint32_t base = su + (uint32_t)st * STG * 2;
#pragma unroll
        for (int c = tid; c < BM * 8; c += NTHR) {
            int r = c >> 3, sg = c & 7;
            uint32_t so = (uint32_t)(r * 144 + sg * 16);
            size_t ga = (size_t)(bm + r) * lda + k0 + sg * 8;
            CP16(base + so, Aptr + ga);
        }
#pragma unroll
        for (int c = tid; c < BN * 8; c += NTHR) {
            int r = c >> 3, sg = c & 7;
            uint32_t so = (uint32_t)(r * 144 + sg * 16);
            size_t gb = (size_t)(bn + r) * ldb + k0 + sg * 8;
            CP16(base + ASZ * 2 + so, Bhi + gb);
            if constexpr (TWOB)
                CP16(base + (ASZ + BSZ) * 2 + so, Blo + gb);
        }
    };

    uint32_t ah[2][MT][4], bh[2][NT][2], bl[2][NT][2];

    const int nk = K / 64;
    load_stage(0, 0);
    CP_COMMIT();

    for (int kt = 0; kt < nk; kt++) {
        const int buf = kt & 1;
        if (kt + 1 < nk) {
            load_stage((kt + 1) & 1, (kt + 1) * 64);
            CP_COMMIT();
            CP_WAIT1();
        } else {
            CP_WAIT0();
        }
        __syncthreads();

        const uint32_t uAh = su + (uint32_t)buf * STG * 2;
        const uint32_t uBh = uAh + ASZ * 2;
        const uint32_t uBl = uAh + (ASZ + BSZ) * 2;

        auto ldfrag = [&](int kk, int pb) {
#pragma unroll
            for (int mt = 0; mt < MT; mt++) {
                uint32_t off = (uint32_t)((wm0 + mt*16 + rowA) * 72 + kk*16 + kselA) * 2;
                ldm_x4(ah[pb][mt], uAh + off);
            }
#pragma unroll
            for (int g = 0; g < 2; g++) {
                uint32_t off = (uint32_t)((wn0 + g*16 + rowB) * 72 + kk*16 + kselB) * 2;
                uint32_t r4[4];
                ldm_x4(r4, uBh + off);
                bh[pb][2*g][0] = r4[0]; bh[pb][2*g][1] = r4[1];
                bh[pb][2*g+1][0] = r4[2]; bh[pb][2*g+1][1] = r4[3];
                if constexpr (TWOB) {
                    ldm_x4(r4, uBl + off);
                    bl[pb][2*g][0] = r4[0]; bl[pb][2*g][1] = r4[1];
                    bl[pb][2*g+1][0] = r4[2]; bl[pb][2*g+1][1] = r4[3];
                }
            }
        };

        ldfrag(0, 0);
#pragma unroll
        for (int kk = 0; kk < 4; kk++) {
            const int pb = kk & 1;
            if (kk < 3) ldfrag(kk + 1, (kk + 1) & 1);
#pragma unroll
            for (int mt = 0; mt < MT; mt++)
#pragma unroll
                for (int nt = 0; nt < NT; nt++)
                    mma16816(acc[mt][nt], ah[pb][mt], bh[pb][nt]);
            if constexpr (TWOB) {
#pragma unroll
                for (int mt = 0; mt < MT; mt++)
#pragma unroll
                    for (int nt = 0; nt < NT; nt++)
                        mma16816(acc[mt][nt], ah[pb][mt], bl[pb][nt]);
            }
        }
        __syncthreads();
    }

    // ---- epilogue: CTA-uniform routing ----
    const int crow = lane >> 2, ccol = (lane & 3) * 2;
    float* Cf = nullptr;  __half *Sh = nullptr;
    int ldc = 0, ldcs = 0, col0 = bn;
    bool doAcc = false, doWF = false, doSH = false;

    if constexpr (MODE == 1) {
        if (bn < 2048)      { Cf = F0; ldc = 2048; col0 = bn;        doWF = true; }
        else if (bn < 2560) { Cf = F1; ldc = 512;  col0 = bn - 2048; doWF = true; }
        else if (bn < 3072) { Cf = F2; ldc = 512;  col0 = bn - 2560; doWF = true; }
        else                { Sh = H0; ldcs = 384; col0 = bn - 3072; doSH = true; }
    } else if constexpr (MODE == 2) {
        if (bn < 2048)      { Cf = F0; ldc = 2048; col0 = bn;        doAcc = true; doWF = true; }
        else if (bn < 2560) { Cf = F1; ldc = 512;  col0 = bn - 2048; doAcc = true; doWF = true; }
        else { Cf = F2; ldc = 512; col0 = bn - 2560; doAcc = true;
               Sh = H0; ldcs = 512; doSH = true; }
    } else if constexpr (MODE == 3) {
        if (bn < 2048)      { Cf = F0; ldc = 2048; col0 = bn;        doWF = true; }
        else                { Sh = H0; ldcs = 128; col0 = bn - 2048; doSH = true; }
    } else {
        Cf = F0; ldc = 2048; col0 = bn; doAcc = true; doWF = true;
    }

#pragma unroll
    for (int mt = 0; mt < MT; mt++) {
#pragma unroll
        for (int nt = 0; nt < NT; nt++) {
            int r0 = bm + wm0 + mt*16 + crow;
            int c0 = col0 + wn0 + nt*8 + ccol;
            float v00 = acc[mt][nt][0], v01 = acc[mt][nt][1];
            float v10 = acc[mt][nt][2], v11 = acc[mt][nt][3];
            if (doAcc) {
                float2 o0 = *(float2*)&Cf[(size_t)r0 * ldc + c0];
                float2 o1 = *(float2*)&Cf[(size_t)(r0+8) * ldc + c0];
                v00 += o0.x; v01 += o0.y; v10 += o1.x; v11 += o1.y;
            }
            if (doWF) {
                *(float2*)&Cf[(size_t)r0 * ldc + c0]     = make_float2(v00, v01);
                *(float2*)&Cf[(size_t)(r0+8) * ldc + c0] = make_float2(v10, v11);
            }
            if (doSH) {
                *(uint32_t*)&Sh[(size_t)r0 * ldcs + c0]     = packh2(v00, v01);
                *(uint32_t*)&Sh[(size_t)(r0+8) * ldcs + c0] = packh2(v10, v11);
            }
        }
    }
}

// ============================================================
// Tensor-core flash attention — single-pass fp16 (R12 best).
// ============================================================
static constexpr int AQ_H = 0;
static constexpr int ASTG = 17408;
static constexpr int AVH = 8704;
static constexpr int ATTN_SMEM_BYTES = (17408 + 2 * ASTG) * 2;  // 104448

__global__ void __launch_bounds__(256, 2) attn_mma_kernel(
    const __half* __restrict__ qh,
    const __half* __restrict__ kh,
    const __half* __restrict__ vh,
    __half* __restrict__ aoh)
{
    extern __shared__ char dynsm[];
    __half* sm = (__half*)dynsm;
    const int qb = blockIdx.x, h = blockIdx.y, b = blockIdx.z;
    const int i0 = qb * 128;
    const int tid = threadIdx.x, lane = tid & 31, warp = tid >> 5;
    const int kvh = h >> 2;
    const uint32_t su = smem_u32(sm);

#pragma unroll
    for (int c = tid; c < 128 * 16; c += 256) {
        int r = c >> 4, sg = c & 15;
        size_t g = ((size_t)(b*S + i0 + r)) * (H*HD) + h*HD + sg*8;
        *(uint4*)&sm[AQ_H + r*136 + sg*8] = *(const uint4*)(qh + g);
    }

    float O[16][4];
#pragma unroll
    for (int i = 0; i < 16; i++)
#pragma unroll
        for (int t = 0; t < 4; t++) O[i][t] = 0.f;
    float m0 = -1e30f, m1 = -1e30f, l0 = 0.f, l1 = 0.f;

    const int rowA = ((lane >> 3) & 1) * 8 + (lane & 7);
    const int kselA = (lane >> 4) * 8;
    const int rowB = ((lane >> 4) & 1) * 8 + (lane & 7);
    const int kselB = ((lane >> 3) & 1) * 8;
    const int rowV = ((lane >> 3) & 1) * 8 + (lane & 7);
    const int colV = (lane >> 4) * 8;

    int startb = 2*qb - 8; if (startb < 1) startb = 1;
    const int kb_end = 2*qb + 1;
    const int nblk = 1 + (kb_end - startb + 1);

    const int ir0 = i0 + warp*16 + (lane >> 2);
    const int ir1 = ir0 + 8;

    auto kbof = [&](int i) { return (i == 0) ? 0 : (startb + i - 1); };
    auto load_kv = [&](int st, int kb) {
        uint32_t base = su + (uint32_t)(17408 + ASTG * st) * 2;
#pragma unroll
        for (int c = tid; c < 64 * 16; c += 256) {
            int r = c >> 4, sg = c & 15;
            size_t g = ((size_t)(b*S + kb*64 + r)) * (KVH*HD) + kvh*HD + sg*8;
            uint32_t so = (uint32_t)(r*136 + sg*8) * 2;
            CP16(base + so, kh + g);
            CP16(base + AVH*2 + so, vh + g);
        }
    };

    load_kv(0, kbof(0));
    CP_COMMIT();
    if (nblk > 1) { load_kv(1, kbof(1)); CP_COMMIT(); }

    for (int bi = 0; bi < nblk; bi++) {
        if (bi + 1 < nblk) CP_WAIT1(); else CP_WAIT0();
        __syncthreads();
        const int kb = kbof(bi);
        const uint32_t sb2 = su + (uint32_t)(17408 + ASTG * (bi & 1)) * 2;

        float sc[8][4];
#pragma unroll
        for (int i = 0; i < 8; i++)
#pragma unroll
            for (int t = 0; t < 4; t++) sc[i][t] = 0.f;

#pragma unroll
        for (int kk = 0; kk < 8; kk++) {
            uint32_t ah[4];
            uint32_t offA = (uint32_t)((warp*16 + rowA)*136 + kk*16 + kselA) * 2;
            ldm_x4(ah, su + AQ_H*2 + offA);
#pragma unroll
            for (int g2 = 0; g2 < 4; g2++) {
                uint32_t bh4[4];
                uint32_t offB = (uint32_t)((g2*16 + rowB)*136 + kk*16 + kselB) * 2;
                ldm_x4(bh4, sb2 + offB);
                mma16816(sc[2*g2],   ah, bh4);
                mma16816(sc[2*g2+1], ah, bh4 + 2);
            }
        }

        const int jb = kb*64 + (lane & 3) * 2;
        float mx0 = -1e30f, mx1 = -1e30f;
#pragma unroll
        for (int nt = 0; nt < 8; nt++) {
            int j0 = jb + nt*8, j1 = j0 + 1;
            if (!((j0 <= ir0) && (((ir0 - j0) < WINDOW) || (j0 < GLOBALK)))) sc[nt][0] = -1e30f;
            if (!((j1 <= ir0) && (((ir0 - j1) < WINDOW) || (j1 < GLOBALK)))) sc[nt][1] = -1e30f;
            if (!((j0 <= ir1) && (((ir1 - j0) < WINDOW) || (j0 < GLOBALK)))) sc[nt][2] = -1e30f;
            if (!((j1 <= ir1) && (((ir1 - j1) < WINDOW) || (j1 < GLOBALK)))) sc[nt][3] = -1e30f;
            mx0 = fmaxf(mx0, fmaxf(sc[nt][0], sc[nt][1]));
            mx1 = fmaxf(mx1, fmaxf(sc[nt][2], sc[nt][3]));
        }
        mx0 = fmaxf(mx0, __shfl_xor_sync(0xffffffffu, mx0, 1));
        mx0 = fmaxf(mx0, __shfl_xor_sync(0xffffffffu, mx0, 2));
        mx1 = fmaxf(mx1, __shfl_xor_sync(0xffffffffu, mx1, 1));
        mx1 = fmaxf(mx1, __shfl_xor_sync(0xffffffffu, mx1, 2));

        float nm0 = fmaxf(m0, mx0), nm1 = fmaxf(m1, mx1);
        float a0 = __expf(m0 - nm0), a1 = __expf(m1 - nm1);
        float s0 = 0.f, s1 = 0.f;
#pragma unroll
        for (int nt = 0; nt < 8; nt++) {
            sc[nt][0] = __expf(sc[nt][0] - nm0);
            sc[nt][1] = __expf(sc[nt][1] - nm0);
            sc[nt][2] = __expf(sc[nt][2] - nm1);
            sc[nt][3] = __expf(sc[nt][3] - nm1);
            s0 += sc[nt][0] + sc[nt][1];
            s1 += sc[nt][2] + sc[nt][3];
        }
        s0 += __shfl_xor_sync(0xffffffffu, s0, 1);
        s0 += __shfl_xor_sync(0xffffffffu, s0, 2);
        s1 += __shfl_xor_sync(0xffffffffu, s1, 1);
        s1 += __shfl_xor_sync(0xffffffffu, s1, 2);
        l0 = l0 * a0 + s0;  l1 = l1 * a1 + s1;
        m0 = nm0;  m1 = nm1;
#pragma unroll
        for (int dt = 0; dt < 16; dt++) {
            O[dt][0] *= a0; O[dt][1] *= a0;
            O[dt][2] *= a1; O[dt][3] *= a1;
        }

#pragma unroll
        for (int kk = 0; kk < 4; kk++) {
            uint32_t pah[4];
            pah[0] = packh2(sc[2*kk][0],   sc[2*kk][1]);
            pah[1] = packh2(sc[2*kk][2],   sc[2*kk][3]);
            pah[2] = packh2(sc[2*kk+1][0], sc[2*kk+1][1]);
            pah[3] = packh2(sc[2*kk+1][2], sc[2*kk+1][3]);
#pragma unroll
            for (int dt2 = 0; dt2 < 8; dt2++) {
                uint32_t vbh[4];
                uint32_t offV = (uint32_t)((kk*16 + rowV)*136 + dt2*16 + colV) * 2;
                ldm_x4_t(vbh, sb2 + AVH*2 + offV);
                mma16816(O[2*dt2],   pah, vbh);
                mma16816(O[2*dt2+1], pah, vbh + 2);
            }
        }

        __syncthreads();
        if (bi + 2 < nblk) { load_kv(bi & 1, kbof(bi + 2)); CP_COMMIT(); }
    }

    const float inv0 = 1.f / l0, inv1 = 1.f / l1;
    const size_t rbase0 = ((size_t)(b*S + i0 + warp*16 + (lane >> 2))) * (H*HD);
    const size_t rbase1 = rbase0 + 8 * (size_t)(H*HD);
#pragma unroll
    for (int dt = 0; dt < 16; dt++) {
        int cc = h*HD + dt*8 + (lane & 3) * 2;
        *(uint32_t*)&aoh[rbase0 + cc] = packh2(O[dt][0]*inv0, O[dt][1]*inv0);
        *(uint32_t*)&aoh[rbase1 + cc] = packh2(O[dt][2]*inv1, O[dt][3]*inv1);
    }
}

// ============================================================
// Host side
// ============================================================
static constexpr int SMEM_GEMM_1B = 2 * (128*72 + 64*72) * 2;   // 55296

extern "C" void kernel_launch(void* const* d_in, const int* in_sizes, int n_in,
                              void* d_out, int out_size)
{
    const float* x = (const float*)d_in[0];
    float* out = (float*)d_out;

    float *q, *k, *v;
    __half *xh, *wh, *th, *aoh, *qhp, *khp, *vhp;
    cudaGetSymbolAddress((void**)&q,   g_q);
    cudaGetSymbolAddress((void**)&k,   g_k);
    cudaGetSymbolAddress((void**)&v,   g_v);
    cudaGetSymbolAddress((void**)&xh,  g_xh);
    cudaGetSymbolAddress((void**)&wh,  g_wh);
    cudaGetSymbolAddress((void**)&th,  g_th);
    cudaGetSymbolAddress((void**)&aoh, g_aoh);
    cudaGetSymbolAddress((void**)&qhp, g_qh);
    cudaGetSymbolAddress((void**)&khp, g_kh);
    cudaGetSymbolAddress((void**)&vhp, g_vh);

    auto G1 = gemm_mma<1, false>;
    auto G2 = gemm_mma<2, false>;
    auto G3 = gemm_mma<3, false>;
    auto G4 = gemm_mma<4, false>;

    cudaFuncSetAttribute(G1, cudaFuncAttributeMaxDynamicSharedMemorySize, SMEM_GEMM_1B);
    cudaFuncSetAttribute(G2, cudaFuncAttributeMaxDynamicSharedMemorySize, SMEM_GEMM_1B);
    cudaFuncSetAttribute(G3, cudaFuncAttributeMaxDynamicSharedMemorySize, SMEM_GEMM_1B);
    cudaFuncSetAttribute(G4, cudaFuncAttributeMaxDynamicSharedMemorySize, SMEM_GEMM_1B);
    cudaFuncSetAttribute(attn_mma_kernel,
        cudaFuncAttributeMaxDynamicSharedMemorySize, ATTN_SMEM_BYTES);

    const int M = MROWS;

    // ---- converts ----
    cvtx_kernel<<<(M*D/4 + 255)/256, 256>>>(x, xh, M*D/4);
    cvtw_kernel<<<(3047424 + 255)/256, 256>>>(
        (const float*)d_in[1], (const float*)d_in[2], (const float*)d_in[3],
        (const float*)d_in[4], (const float*)d_in[5], (const float*)d_in[6],
        (const float*)d_in[7], (const float*)d_in[8], (const float*)d_in[9],
        (const float*)d_in[10], (const float*)d_in[11], (const float*)d_in[12],
        wh);

    // ---- G1: q|k|v|th = x @ [wq_w; wk_w; wv_w; wq_a; wk_a; wv_a]^T ----
    G1<<<dim3(3456/64, 32), 256, SMEM_GEMM_1B>>>(
        xh, D, wh+OFF_QKVW, nullptr, D,
        q, k, v, th, M, 3456, D);

    // ---- G2: fused LoRA b-projections (v-range writes vh) ----
    G2<<<dim3(3072/64, 32), 256, SMEM_GEMM_1B>>>(
        th, 384, wh+OFF_QB, nullptr, 128,
        q, k, v, vhp, M, 3072, 128);

    // ---- RoPE + fp16 convert (hi only) ----
    {
        int tq = M * H * 64;
        rope_split_kernel<<<(tq + 255)/256, 256>>>(q, qhp, H, SCALE, tq);
        int tk = M * KVH * 64;
        rope_split_kernel<<<(tk + 255)/256, 256>>>(k, khp, KVH, 1.0f, tk);
    }

    // ---- attention (single-pass fp16) ----
    {
        dim3 grid(S/128, H, B);
        attn_mma_kernel<<<grid, 256, ATTN_SMEM_BYTES>>>(qhp, khp, vhp, aoh);
    }

    // ---- G3: out|th = ao @ [wo_w; wo_a]^T ----
    G3<<<dim3(2176/64, 32), 256, SMEM_GEMM_1B>>>(
        aoh, 2048, wh+OFF_OW, nullptr, 2048,
        out, nullptr, nullptr, th, M, 2176, 2048);

    // ---- G4: out += th @ wo_b^T ----
    G4<<<dim3(2048/64, 32), 256, SMEM_GEMM_1B>>>(
        th, 128, wh+OFF_OB, nullptr, 128,
        out, nullptr, nullptr, nullptr, M, 2048, 128);
}

// round 16
// speedup vs baseline: 2.2150x; 1.9319x over previous
#include <cuda_runtime.h>
#include <cuda_fp16.h>
#include <math.h>
#include <stdint.h>

// Problem constants
static constexpr int B = 2, S = 2048, D = 2048;
static constexpr int H = 16, KVH = 4, HD = 128;
static constexpr int MROWS = B * S;            // 4096
static constexpr int WINDOW = 512, GLOBALK = 64;
static constexpr float SCALE = 0.08838834764831845f;  // 1/sqrt(128)

// ------------- scratch (device globals) -------------
__device__ __half g_xh[(size_t)MROWS * D];
__device__ __half g_wh[12189696];
__device__ __half g_th[(size_t)MROWS * 384];
__device__ __half g_aoh[(size_t)MROWS * (H * HD)];
__device__ __half g_qh[(size_t)MROWS * (H * HD)];
__device__ __half g_kh[(size_t)MROWS * (KVH * HD)];
__device__ __half g_vh[(size_t)MROWS * (KVH * HD)];

// weight pool layout (elements)
static constexpr size_t OFF_QKVW = 0;          // [wq_w;wk_w;wv_w] 3072 x 2048
static constexpr size_t OFF_A    = 6291456;    // [wq_a;wk_a;wv_a] 384 x 2048
static constexpr size_t OFF_QB   = 7077888;    // [wq_b;wk_b;wv_b] 3072 x 128
static constexpr size_t OFF_OW   = 7471104;    // [wo_w;wo_a] 2176 x 2048
static constexpr size_t OFF_OB   = 11927552;   // wo_b 2048 x 128

// ============================================================
// helpers
// ============================================================
__device__ __forceinline__ uint32_t smem_u32(const void* p) {
    uint32_t a;
    asm("{ .reg .u64 t; cvta.to.shared.u64 t, %1; cvt.u32.u64 %0, t; }"
        : "=r"(a) : "l"(p));
    return a;
}
__device__ __forceinline__ void ldm_x4(uint32_t* r, uint32_t addr) {
    asm volatile("ldmatrix.sync.aligned.m8n8.x4.shared.b16 {%0,%1,%2,%3}, [%4];"
                 : "=r"(r[0]), "=r"(r[1]), "=r"(r[2]), "=r"(r[3]) : "r"(addr));
}
__device__ __forceinline__ void ldm_x4_t(uint32_t* r, uint32_t addr) {
    asm volatile("ldmatrix.sync.aligned.m8n8.x4.trans.shared.b16 {%0,%1,%2,%3}, [%4];"
                 : "=r"(r[0]), "=r"(r[1]), "=r"(r[2]), "=r"(r[3]) : "r"(addr));
}
__device__ __forceinline__ void mma16816(float* c, const uint32_t* a, const uint32_t* b) {
    asm volatile(
        "mma.sync.aligned.m16n8k16.row.col.f32.f16.f16.f32 "
        "{%0,%1,%2,%3}, {%4,%5,%6,%7}, {%8,%9}, {%0,%1,%2,%3};"
        : "+f"(c[0]), "+f"(c[1]), "+f"(c[2]), "+f"(c[3])
        : "r"(a[0]), "r"(a[1]), "r"(a[2]), "r"(a[3]), "r"(b[0]), "r"(b[1]));
}
#define CP16(saddr, gptr) \
    asm volatile("cp.async.cg.shared.global [%0], [%1], 16;" :: "r"(saddr), "l"(gptr))
#define CP_COMMIT() asm volatile("cp.async.commit_group;" ::: "memory")
#define CP_WAIT0()  asm volatile("cp.async.wait_group 0;" ::: "memory")
#define CP_WAIT1()  asm volatile("cp.async.wait_group 1;" ::: "memory")

__device__ __forceinline__ uint32_t packh2(float x, float y) {
    __half2 h = __floats2half2_rn(x, y);
    return *(uint32_t*)&h;
}

// ============================================================
// converters
// ============================================================
__global__ void cvtx_kernel(const float* __restrict__ x,
                            __half* __restrict__ hi, int n4)
{
    int i = blockIdx.x * 256 + threadIdx.x;
    if (i >= n4) return;
    float4 v = ((const float4*)x)[i];
    __half h[4] = { __float2half_rn(v.x), __float2half_rn(v.y),
                    __float2half_rn(v.z), __float2half_rn(v.w) };
    *(uint2*)&hi[4*(size_t)i] = *(uint2*)h;
}

__global__ void cvtw_kernel(
    const float* p0, const float* p1, const float* p2, const float* p3,
    const float* p4, const float* p5, const float* p6, const float* p7,
    const float* p8, const float* p9, const float* p10, const float* p11,
    __half* __restrict__ hi)
{
    const float* srcs[12] = {p0,p1,p2,p3,p4,p5,p6,p7,p8,p9,p10,p11};
    const int pre[13] = {0, 1048576, 1114112, 1179648, 1441792, 1507328,
                         1523712, 1785856, 1851392, 1867776, 2916352,
                         2981888, 3047424};
    const int dst[12] = {0, 1572864, 1769472, 1048576, 1638400, 1835008,
                         1310720, 1703936, 1851392, 1867776, 2916352, 2981888};
    int gi = blockIdx.x * 256 + threadIdx.x;
    if (gi >= 3047424) return;
    int s = 0;
#pragma unroll
    for (int t = 1; t < 12; t++) if (gi >= pre[t]) s = t;
    int local = gi - pre[s];
    float4 v = ((const float4*)srcs[s])[local];
    __half h[4] = { __float2half_rn(v.x), __float2half_rn(v.y),
                    __float2half_rn(v.z), __float2half_rn(v.w) };
    size_t o = 4 * ((size_t)dst[s] + local);
    *(uint2*)&hi[o] = *(uint2*)h;
}

// ============================================================
// mma.sync GEMM (R15 best config + fused-K + rope epilogue):
// 128x64 CTA tile, 8 warps (4x2 of 32x32), K-chunk 64 (stride 72),
// 2-stage cp.async, register double-buffered fragments, single-pass.
// MODE 0 (TH):  th = fp16(x @ A^T), ld 384
// MODE 1 (QKV): fused K=2176 ([x|th_sec] @ [W|Bw]^T), rope epilogue,
//               writes qh/kh/vh fp16 directly
// MODE 3 (OUT): out fp32 (cols<2048) | th fp16 ld 128 (rest)
// MODE 4 (ACC): out += A @ B^T
// ============================================================
template<int MODE>
__global__ void __launch_bounds__(256, 2) gemm_mma(
    const __half* __restrict__ A1, const __half* __restrict__ A2,
    const __half* __restrict__ B1, const __half* __restrict__ B2,
    float* __restrict__ F0,
    __half* __restrict__ H0, __half* __restrict__ H1, __half* __restrict__ H2,
    const int M, const int N, const int K)
{
    constexpr int BM = 128, BN = 64;
    constexpr int NTHR = 256, MT = 2, NT = 4;
    constexpr int ASZ = BM * 72, BSZ = BN * 72;  // halves
    constexpr int STG = ASZ + BSZ;
    constexpr int LDA1 = (MODE == 4) ? 128 : 2048;
    constexpr int LDB1 = (MODE == 4) ? 128 : 2048;
    extern __shared__ char dynsm[];
    __half* smem = (__half*)dynsm;

    const int tid = threadIdx.x, lane = tid & 31, warp = tid >> 5;
    const int bm = blockIdx.y * BM;
    const int bn = blockIdx.x * BN;
    const int wm0 = (warp >> 1) * 32, wn0 = (warp & 1) * 32;
    const uint32_t su = smem_u32(smem);

    int sec = 0;
    if constexpr (MODE == 1)
        sec = (bn < 2048) ? 0 : (bn < 2560 ? 128 : 256);

    const int rowA = ((lane >> 3) & 1) * 8 + (lane & 7);
    const int kselA = (lane >> 4) * 8;
    const int rowB = ((lane >> 4) & 1) * 8 + (lane & 7);
    const int kselB = ((lane >> 3) & 1) * 8;

    float acc[MT][NT][4];
#pragma unroll
    for (int i = 0; i < MT; i++)
#pragma unroll
        for (int j = 0; j < NT; j++)
#pragma unroll
            for (int t = 0; t < 4; t++) acc[i][j][t] = 0.f;

    auto load_stage = [&](int st, int k0) {
        uint32_t base = su + (uint32_t)st * STG * 2;
        const __half* Ap;  const __half* Bp;
        int la, lb, ko = k0;
        if constexpr (MODE == 1) {
            if (k0 >= 2048) { Ap = A2 + sec; la = 384; Bp = B2; lb = 128; ko = k0 - 2048; }
            else            { Ap = A1;       la = 2048; Bp = B1; lb = 2048; }
        } else {
            Ap = A1; la = LDA1; Bp = B1; lb = LDB1;
        }
#pragma unroll
        for (int c = tid; c < BM * 8; c += NTHR) {
            int r = c >> 3, sg = c & 7;
            uint32_t so = (uint32_t)(r * 144 + sg * 16);
            size_t ga = (size_t)(bm + r) * la + ko + sg * 8;
            CP16(base + so, Ap + ga);
        }
#pragma unroll
        for (int c = tid; c < BN * 8; c += NTHR) {
            int r = c >> 3, sg = c & 7;
            uint32_t so = (uint32_t)(r * 144 + sg * 16);
            size_t gb = (size_t)(bn + r) * lb + ko + sg * 8;
            CP16(base + ASZ * 2 + so, Bp + gb);
        }
    };

    uint32_t ah[2][MT][4], bh[2][NT][2];

    const int nk = K / 64;
    load_stage(0, 0);
    CP_COMMIT();

    for (int kt = 0; kt < nk; kt++) {
        const int buf = kt & 1;
        if (kt + 1 < nk) {
            load_stage((kt + 1) & 1, (kt + 1) * 64);
            CP_COMMIT();
            CP_WAIT1();
        } else {
            CP_WAIT0();
        }
        __syncthreads();

        const uint32_t uAh = su + (uint32_t)buf * STG * 2;
        const uint32_t uBh = uAh + ASZ * 2;

        auto ldfrag = [&](int kk, int pb) {
#pragma unroll
            for (int mt = 0; mt < MT; mt++) {
                uint32_t off = (uint32_t)((wm0 + mt*16 + rowA) * 72 + kk*16 + kselA) * 2;
                ldm_x4(ah[pb][mt], uAh + off);
            }
#pragma unroll
            for (int g = 0; g < 2; g++) {
                uint32_t off = (uint32_t)((wn0 + g*16 + rowB) * 72 + kk*16 + kselB) * 2;
                uint32_t r4[4];
                ldm_x4(r4, uBh + off);
                bh[pb][2*g][0] = r4[0]; bh[pb][2*g][1] = r4[1];
                bh[pb][2*g+1][0] = r4[2]; bh[pb][2*g+1][1] = r4[3];
            }
        };

        ldfrag(0, 0);
#pragma unroll
        for (int kk = 0; kk < 4; kk++) {
            const int pb = kk & 1;
            if (kk < 3) ldfrag(kk + 1, (kk + 1) & 1);
#pragma unroll
            for (int mt = 0; mt < MT; mt++)
#pragma unroll
                for (int nt = 0; nt < NT; nt++)
                    mma16816(acc[mt][nt], ah[pb][mt], bh[pb][nt]);
        }
        __syncthreads();
    }

    // ---- epilogue ----
    const int crow = lane >> 2, ccol = (lane & 3) * 2;

    if constexpr (MODE == 1) {
        __half* Sh;  int ldcs, col0;  float rscale = 1.f;  bool doRope;
        if (bn < 2048)      { Sh = H0; ldcs = 2048; col0 = bn;        rscale = SCALE; doRope = true; }
        else if (bn < 2560) { Sh = H1; ldcs = 512;  col0 = bn - 2048; doRope = true; }
        else                { Sh = H2; ldcs = 512;  col0 = bn - 2560; doRope = false; }
#pragma unroll
        for (int nt = 0; nt < NT; nt++) {
            int c0 = col0 + wn0 + nt*8 + ccol;
            float invf = 0.f;
            if (doRope) {
                int d = (c0 & 127) >> 1;
                invf = (float)pow(1.0e6, -(double)d / 64.0);
            }
#pragma unroll
            for (int mt = 0; mt < MT; mt++) {
                int r0 = bm + wm0 + mt*16 + crow;
                float v00 = acc[mt][nt][0], v01 = acc[mt][nt][1];
                float v10 = acc[mt][nt][2], v11 = acc[mt][nt][3];
                if (doRope) {
                    float sn, cs;
                    sincosf((float)(r0 & 2047) * invf, &sn, &cs);
                    float a0 = (v00*cs - v01*sn) * rscale;
                    float a1 = (v00*sn + v01*cs) * rscale;
                    *(uint32_t*)&Sh[(size_t)r0 * ldcs + c0] = packh2(a0, a1);
                    sincosf((float)((r0+8) & 2047) * invf, &sn, &cs);
                    a0 = (v10*cs - v11*sn) * rscale;
                    a1 = (v10*sn + v11*cs) * rscale;
                    *(uint32_t*)&Sh[(size_t)(r0+8) * ldcs + c0] = packh2(a0, a1);
                } else {
                    *(uint32_t*)&Sh[(size_t)r0 * ldcs + c0]     = packh2(v00, v01);
                    *(uint32_t*)&Sh[(size_t)(r0+8) * ldcs + c0] = packh2(v10, v11);
                }
            }
        }
        return;
    }

    float* Cf = nullptr;  __half* Sh = nullptr;
    int ldc = 0, ldcs = 0, col0 = bn;
    bool doAcc = false, doWF = false, doSH = false;

    if constexpr (MODE == 0) {
        Sh = H0; ldcs = 384; col0 = bn; doSH = true;
    } else if constexpr (MODE == 3) {
        if (bn < 2048)      { Cf = F0; ldc = 2048; col0 = bn;        doWF = true; }
        else                { Sh = H0; ldcs = 128; col0 = bn - 2048; doSH = true; }
    } else {  // MODE 4
        Cf = F0; ldc = 2048; col0 = bn; doAcc = true; doWF = true;
    }

#pragma unroll
    for (int mt = 0; mt < MT; mt++) {
#pragma unroll
        for (int nt = 0; nt < NT; nt++) {
            int r0 = bm + wm0 + mt*16 + crow;
            int c0 = col0 + wn0 + nt*8 + ccol;
            float v00 = acc[mt][nt][0], v01 = acc[mt][nt][1];
            float v10 = acc[mt][nt][2], v11 = acc[mt][nt][3];
            if (doAcc) {
                float2 o0 = *(float2*)&Cf[(size_t)r0 * ldc + c0];
                float2 o1 = *(float2*)&Cf[(size_t)(r0+8) * ldc + c0];
                v00 += o0.x; v01 += o0.y; v10 += o1.x; v11 += o1.y;
            }
            if (doWF) {
                *(float2*)&Cf[(size_t)r0 * ldc + c0]     = make_float2(v00, v01);
                *(float2*)&Cf[(size_t)(r0+8) * ldc + c0] = make_float2(v10, v11);
            }
            if (doSH) {
                *(uint32_t*)&Sh[(size_t)r0 * ldcs + c0]     = packh2(v00, v01);
                *(uint32_t*)&Sh[(size_t)(r0+8) * ldcs + c0] = packh2(v10, v11);
            }
        }
    }
}

// ============================================================
// Tensor-core flash attention — single-pass fp16 (R12/R15 best).
// ============================================================
static constexpr int AQ_H = 0;
static constexpr int ASTG = 17408;
static constexpr int AVH = 8704;
static constexpr int ATTN_SMEM_BYTES = (17408 + 2 * ASTG) * 2;  // 104448

__global__ void __launch_bounds__(256, 2) attn_mma_kernel(
    const __half* __restrict__ qh,
    const __half* __restrict__ kh,
    const __half* __restrict__ vh,
    __half* __restrict__ aoh)
{
    extern __shared__ char dynsm[];
    __half* sm = (__half*)dynsm;
    const int qb = blockIdx.x, h = blockIdx.y, b = blockIdx.z;
    const int i0 = qb * 128;
    const int tid = threadIdx.x, lane = tid & 31, warp = tid >> 5;
    const int kvh = h >> 2;
    const uint32_t su = smem_u32(sm);

#pragma unroll
    for (int c = tid; c < 128 * 16; c += 256) {
        int r = c >> 4, sg = c & 15;
        size_t g = ((size_t)(b*S + i0 + r)) * (H*HD) + h*HD + sg*8;
        *(uint4*)&sm[AQ_H + r*136 + sg*8] = *(const uint4*)(qh + g);
    }

    float O[16][4];
#pragma unroll
    for (int i = 0; i < 16; i++)
#pragma unroll
        for (int t = 0; t < 4; t++) O[i][t] = 0.f;
    float m0 = -1e30f, m1 = -1e30f, l0 = 0.f, l1 = 0.f;

    const int rowA = ((lane >> 3) & 1) * 8 + (lane & 7);
    const int kselA = (lane >> 4) * 8;
    const int rowB = ((lane >> 4) & 1) * 8 + (lane & 7);
    const int kselB = ((lane >> 3) & 1) * 8;
    const int rowV = ((lane >> 3) & 1) * 8 + (lane & 7);
    const int colV = (lane >> 4) * 8;

    int startb = 2*qb - 8; if (startb < 1) startb = 1;
    const int kb_end = 2*qb + 1;
    const int nblk = 1 + (kb_end - startb + 1);

    const int ir0 = i0 + warp*16 + (lane >> 2);
    const int ir1 = ir0 + 8;

    auto kbof = [&](int i) { return (i == 0) ? 0 : (startb + i - 1); };
    auto load_kv = [&](int st, int kb) {
        uint32_t base = su + (uint32_t)(17408 + ASTG * st) * 2;
#pragma unroll
        for (int c = tid; c < 64 * 16; c += 256) {
            int r = c >> 4, sg = c & 15;
            size_t g = ((size_t)(b*S + kb*64 + r)) * (KVH*HD) + kvh*HD + sg*8;
            uint32_t so = (uint32_t)(r*136 + sg*8) * 2;
            CP16(base + so, kh + g);
            CP16(base + AVH*2 + so, vh + g);
        }
    };

    load_kv(0, kbof(0));
    CP_COMMIT();
    if (nblk > 1) { load_kv(1, kbof(1)); CP_COMMIT(); }

    for (int bi = 0; bi < nblk; bi++) {
        if (bi + 1 < nblk) CP_WAIT1(); else CP_WAIT0();
        __syncthreads();
        const int kb = kbof(bi);
        const uint32_t sb2 = su + (uint32_t)(17408 + ASTG * (bi & 1)) * 2;

        float sc[8][4];
#pragma unroll
        for (int i = 0; i < 8; i++)
#pragma unroll
            for (int t = 0; t < 4; t++) sc[i][t] = 0.f;

#pragma unroll
        for (int kk = 0; kk < 8; kk++) {
            uint32_t ah[4];
            uint32_t offA = (uint32_t)((warp*16 + rowA)*136 + kk*16 + kselA) * 2;
            ldm_x4(ah, su + AQ_H*2 + offA);
#pragma unroll
            for (int g2 = 0; g2 < 4; g2++) {
                uint32_t bh4[4];
                uint32_t offB = (uint32_t)((g2*16 + rowB)*136 + kk*16 + kselB) * 2;
                ldm_x4(bh4, sb2 + offB);
                mma16816(sc[2*g2],   ah, bh4);
                mma16816(sc[2*g2+1], ah, bh4 + 2);
            }
        }

        const int jb = kb*64 + (lane & 3) * 2;
        float mx0 = -1e30f, mx1 = -1e30f;
#pragma unroll
        for (int nt = 0; nt < 8; nt++) {
            int j0 = jb + nt*8, j1 = j0 + 1;
            if (!((j0 <= ir0) && (((ir0 - j0) < WINDOW) || (j0 < GLOBALK)))) sc[nt][0] = -1e30f;
            if (!((j1 <= ir0) && (((ir0 - j1) < WINDOW) || (j1 < GLOBALK)))) sc[nt][1] = -1e30f;
            if (!((j0 <= ir1) && (((ir1 - j0) < WINDOW) || (j0 < GLOBALK)))) sc[nt][2] = -1e30f;
            if (!((j1 <= ir1) && (((ir1 - j1) < WINDOW) || (j1 < GLOBALK)))) sc[nt][3] = -1e30f;
            mx0 = fmaxf(mx0, fmaxf(sc[nt][0], sc[nt][1]));
            mx1 = fmaxf(mx1, fmaxf(sc[nt][2], sc[nt][3]));
        }
        mx0 = fmaxf(mx0, __shfl_xor_sync(0xffffffffu, mx0, 1));
        mx0 = fmaxf(mx0, __shfl_xor_sync(0xffffffffu, mx0, 2));
        mx1 = fmaxf(mx1, __shfl_xor_sync(0xffffffffu, mx1, 1));
        mx1 = fmaxf(mx1, __shfl_xor_sync(0xffffffffu, mx1, 2));

        float nm0 = fmaxf(m0, mx0), nm1 = fmaxf(m1, mx1);
        float a0 = __expf(m0 - nm0), a1 = __expf(m1 - nm1);
        float s0 = 0.f, s1 = 0.f;
#pragma unroll
        for (int nt = 0; nt < 8; nt++) {
            sc[nt][0] = __expf(sc[nt][0] - nm0);
            sc[nt][1] = __expf(sc[nt][1] - nm0);
            sc[nt][2] = __expf(sc[nt][2] - nm1);
            sc[nt][3] = __expf(sc[nt][3] - nm1);
            s0 += sc[nt][0] + sc[nt][1];
            s1 += sc[nt][2] + sc[nt][3];
        }
        s0 += __shfl_xor_sync(0xffffffffu, s0, 1);
        s0 += __shfl_xor_sync(0xffffffffu, s0, 2);
        s1 += __shfl_xor_sync(0xffffffffu, s1, 1);
        s1 += __shfl_xor_sync(0xffffffffu, s1, 2);
        l0 = l0 * a0 + s0;  l1 = l1 * a1 + s1;
        m0 = nm0;  m1 = nm1;
#pragma unroll
        for (int dt = 0; dt < 16; dt++) {
            O[dt][0] *= a0; O[dt][1] *= a0;
            O[dt][2] *= a1; O[dt][3] *= a1;
        }

#pragma unroll
        for (int kk = 0; kk < 4; kk++) {
            uint32_t pah[4];
            pah[0] = packh2(sc[2*kk][0],   sc[2*kk][1]);
            pah[1] = packh2(sc[2*kk][2],   sc[2*kk][3]);
            pah[2] = packh2(sc[2*kk+1][0], sc[2*kk+1][1]);
            pah[3] = packh2(sc[2*kk+1][2], sc[2*kk+1][3]);
#pragma unroll
            for (int dt2 = 0; dt2 < 8; dt2++) {
                uint32_t vbh[4];
                uint32_t offV = (uint32_t)((kk*16 + rowV)*136 + dt2*16 + colV) * 2;
                ldm_x4_t(vbh, sb2 + AVH*2 + offV);
                mma16816(O[2*dt2],   pah, vbh);
                mma16816(O[2*dt2+1], pah, vbh + 2);
            }
        }

        __syncthreads();
        if (bi + 2 < nblk) { load_kv(bi & 1, kbof(bi + 2)); CP_COMMIT(); }
    }

    const float inv0 = 1.f / l0, inv1 = 1.f / l1;
    const size_t rbase0 = ((size_t)(b*S + i0 + warp*16 + (lane >> 2))) * (H*HD);
    const size_t rbase1 = rbase0 + 8 * (size_t)(H*HD);
#pragma unroll
    for (int dt = 0; dt < 16; dt++) {
        int cc = h*HD + dt*8 + (lane & 3) * 2;
        *(uint32_t*)&aoh[rbase0 + cc] = packh2(O[dt][0]*inv0, O[dt][1]*inv0);
        *(uint32_t*)&aoh[rbase1 + cc] = packh2(O[dt][2]*inv1, O[dt][3]*inv1);
    }
}

// ============================================================
// Host side
// ============================================================
static constexpr int SMEM_GEMM = 2 * (128*72 + 64*72) * 2;   // 55296

extern "C" void kernel_launch(void* const* d_in, const int* in_sizes, int n_in,
                              void* d_out, int out_size)
{
    const float* x = (const float*)d_in[0];
    float* out = (float*)d_out;

    __half *xh, *wh, *th, *aoh, *qhp, *khp, *vhp;
    cudaGetSymbolAddress((void**)&xh,  g_xh);
    cudaGetSymbolAddress((void**)&wh,  g_wh);
    cudaGetSymbolAddress((void**)&th,  g_th);
    cudaGetSymbolAddress((void**)&aoh, g_aoh);
    cudaGetSymbolAddress((void**)&qhp, g_qh);
    cudaGetSymbolAddress((void**)&khp, g_kh);
    cudaGetSymbolAddress((void**)&vhp, g_vh);

    auto G0 = gemm_mma<0>;
    auto G1 = gemm_mma<1>;
    auto G3 = gemm_mma<3>;
    auto G4 = gemm_mma<4>;

    cudaFuncSetAttribute(G0, cudaFuncAttributeMaxDynamicSharedMemorySize, SMEM_GEMM);
    cudaFuncSetAttribute(G1, cudaFuncAttributeMaxDynamicSharedMemorySize, SMEM_GEMM);
    cudaFuncSetAttribute(G3, cudaFuncAttributeMaxDynamicSharedMemorySize, SMEM_GEMM);
    cudaFuncSetAttribute(G4, cudaFuncAttributeMaxDynamicSharedMemorySize, SMEM_GEMM);
    cudaFuncSetAttribute(attn_mma_kernel,
        cudaFuncAttributeMaxDynamicSharedMemorySize, ATTN_SMEM_BYTES);

    const int M = MROWS;

    // ---- converts ----
    cvtx_kernel<<<(M*D/4 + 255)/256, 256>>>(x, xh, M*D/4);
    cvtw_kernel<<<(3047424 + 255)/256, 256>>>(
        (const float*)d_in[1], (const float*)d_in[2], (const float*)d_in[3],
        (const float*)d_in[4], (const float*)d_in[5], (const float*)d_in[6],
        (const float*)d_in[7], (const float*)d_in[8], (const float*)d_in[9],
        (const float*)d_in[10], (const float*)d_in[11], (const float*)d_in[12],
        wh);

    // ---- G0: th = fp16(x @ [wq_a;wk_a;wv_a]^T)  (N=384, K=2048) ----
    G0<<<dim3(384/64, 32), 256, SMEM_GEMM>>>(
        xh, nullptr, wh + OFF_A, nullptr,
        nullptr, th, nullptr, nullptr, M, 384, 2048);

    // ---- G1: qh|kh|vh = rope([x|th] @ [W|Bw]^T)  (N=3072, K=2176) ----
    G1<<<dim3(3072/64, 32), 256, SMEM_GEMM>>>(
        xh, th, wh + OFF_QKVW, wh + OFF_QB,
        nullptr, qhp, khp, vhp, M, 3072, 2176);

    // ---- attention (single-pass fp16) ----
    {
        dim3 grid(S/128, H, B);
        attn_mma_kernel<<<grid, 256, ATTN_SMEM_BYTES>>>(qhp, khp, vhp, aoh);
    }

    // ---- G3: out|th = ao @ [wo_w; wo_a]^T  (N=2176, K=2048) ----
    G3<<<dim3(2176/64, 32), 256, SMEM_GEMM>>>(
        aoh, nullptr, wh + OFF_OW, nullptr,
        out, th, nullptr, nullptr, M, 2176, 2048);

    // ---- G4: out += th @ wo_b^T  (N=2048, K=128) ----
    G4<<<dim3(2048/64, 32), 256, SMEM_GEMM>>>(
        th, nullptr, wh + OFF_OB, nullptr,
        out, nullptr, nullptr, nullptr, M, 2048, 128);
}

// round 17
// speedup vs baseline: 2.6619x; 1.2018x over previous
#include <cuda_runtime.h>
#include <cuda_fp16.h>
#include <math.h>
#include <stdint.h>

// Problem constants
static constexpr int B = 2, S = 2048, D = 2048;
static constexpr int H = 16, KVH = 4, HD = 128;
static constexpr int MROWS = B * S;            // 4096
static constexpr int WINDOW = 512, GLOBALK = 64;
static constexpr float SCALE = 0.08838834764831845f;  // 1/sqrt(128)

// ------------- scratch (device globals) -------------
__device__ __half g_xh[(size_t)MROWS * D];
__device__ __half g_wh[12189696];
__device__ __half g_aoh[(size_t)MROWS * (H * HD)];
__device__ __half g_qh[(size_t)MROWS * (H * HD)];
__device__ __half g_kh[(size_t)MROWS * (KVH * HD)];
__device__ __half g_vh[(size_t)MROWS * (KVH * HD)];

// weight pool layout (halves)
static constexpr size_t OFF_QKVW = 0;          // W_eff qkv: 3072 x 2048
static constexpr size_t OFF_A    = 6291456;    // aT pools: 3 x [2048 x 128]
static constexpr size_t OFF_QB   = 7077888;    // b pool: [wq_b;wk_b;wv_b] 3072 x 128
static constexpr size_t OFF_OW   = 7471104;    // W_eff o: 2048 x 2048
static constexpr size_t OFF_OAT  = OFF_OW + (size_t)2048*2048;  // wo_aT 2048 x 128
static constexpr size_t OFF_OB   = 11927552;   // wo_b 2048 x 128

// ============================================================
// helpers
// ============================================================
__device__ __forceinline__ uint32_t smem_u32(const void* p) {
    uint32_t a;
    asm("{ .reg .u64 t; cvta.to.shared.u64 t, %1; cvt.u32.u64 %0, t; }"
        : "=r"(a) : "l"(p));
    return a;
}
__device__ __forceinline__ void ldm_x4(uint32_t* r, uint32_t addr) {
    asm volatile("ldmatrix.sync.aligned.m8n8.x4.shared.b16 {%0,%1,%2,%3}, [%4];"
                 : "=r"(r[0]), "=r"(r[1]), "=r"(r[2]), "=r"(r[3]) : "r"(addr));
}
__device__ __forceinline__ void ldm_x4_t(uint32_t* r, uint32_t addr) {
    asm volatile("ldmatrix.sync.aligned.m8n8.x4.trans.shared.b16 {%0,%1,%2,%3}, [%4];"
                 : "=r"(r[0]), "=r"(r[1]), "=r"(r[2]), "=r"(r[3]) : "r"(addr));
}
__device__ __forceinline__ void mma16816(float* c, const uint32_t* a, const uint32_t* b) {
    asm volatile(
        "mma.sync.aligned.m16n8k16.row.col.f32.f16.f16.f32 "
        "{%0,%1,%2,%3}, {%4,%5,%6,%7}, {%8,%9}, {%0,%1,%2,%3};"
        : "+f"(c[0]), "+f"(c[1]), "+f"(c[2]), "+f"(c[3])
        : "r"(a[0]), "r"(a[1]), "r"(a[2]), "r"(a[3]), "r"(b[0]), "r"(b[1]));
}
#define CP16(saddr, gptr) \
    asm volatile("cp.async.cg.shared.global [%0], [%1], 16;" :: "r"(saddr), "l"(gptr))
#define CP_COMMIT() asm volatile("cp.async.commit_group;" ::: "memory")
#define CP_WAIT0()  asm volatile("cp.async.wait_group 0;" ::: "memory")
#define CP_WAIT1()  asm volatile("cp.async.wait_group 1;" ::: "memory")

__device__ __forceinline__ uint32_t packh2(float x, float y) {
    __half2 h = __floats2half2_rn(x, y);
    return *(uint32_t*)&h;
}

// ============================================================
// converters
// ============================================================
__global__ void cvtx_kernel(const float* __restrict__ x,
                            __half* __restrict__ hi, int n4)
{
    int i = blockIdx.x * 256 + threadIdx.x;
    if (i >= n4) return;
    float4 v = ((const float4*)x)[i];
    __half h[4] = { __float2half_rn(v.x), __float2half_rn(v.y),
                    __float2half_rn(v.z), __float2half_rn(v.w) };
    *(uint2*)&hi[4*(size_t)i] = *(uint2*)h;
}

// b-matrices only: qb, kb, vb, ob -> fp16 pool
__global__ void cvtb_kernel(
    const float* p0, const float* p1, const float* p2, const float* p3,
    __half* __restrict__ hi)
{
    const float* srcs[4] = {p0, p1, p2, p3};
    const int pre[5] = {0, 65536, 81920, 98304, 163840};
    const int dst[4] = {1769472, 1835008, 1851392, 2981888};
    int gi = blockIdx.x * 256 + threadIdx.x;
    if (gi >= 163840) return;
    int s = 0;
#pragma unroll
    for (int t = 1; t < 4; t++) if (gi >= pre[t]) s = t;
    int local = gi - pre[s];
    float4 v = ((const float4*)srcs[s])[local];
    __half h[4] = { __float2half_rn(v.x), __float2half_rn(v.y),
                    __float2half_rn(v.z), __float2half_rn(v.w) };
    size_t o = 4 * ((size_t)dst[s] + local);
    *(uint2*)&hi[o] = *(uint2*)h;
}

// transpose a-matrices [128,2048] fp32 -> [2048,128] fp16
__global__ void transA_kernel(const float* a0, const float* a1,
                              const float* a2, const float* a3,
                              __half* __restrict__ wh)
{
    __shared__ float tile[32][33];
    int mtx = blockIdx.z;
    const float* src = (mtx == 0) ? a0 : (mtx == 1) ? a1 : (mtx == 2) ? a2 : a3;
    size_t dsto = (mtx < 3) ? (OFF_A + (size_t)mtx * 262144) : OFF_OAT;
    int n0 = blockIdx.x * 32, k0 = blockIdx.y * 32;
    int tx = threadIdx.x, ty = threadIdx.y;
#pragma unroll
    for (int j = ty; j < 32; j += 8)
        tile[j][tx] = src[(size_t)(k0 + j) * 2048 + n0 + tx];
    __syncthreads();
#pragma unroll
    for (int j = ty; j < 32; j += 8)
        wh[dsto + (size_t)(n0 + j) * 128 + k0 + tx] = __float2half_rn(tile[tx][j]);
}

// ============================================================
// weight-fuse GEMM: W_eff[m,n] = fp16(Wf32[m,n] + sum_k b[m,k]*aT[n,k])
// M x 2048, K=128. Same tile config as main GEMM.
// Per-CTA row-range selects aT / fp32-W source (qkv: 0/2048/2560).
// ============================================================
__global__ void __launch_bounds__(256, 2) wfuse_mma(
    const __half* __restrict__ Ab,
    const __half* __restrict__ aT0, const __half* __restrict__ aT1,
    const __half* __restrict__ aT2,
    const float* __restrict__ w0, const float* __restrict__ w1,
    const float* __restrict__ w2,
    __half* __restrict__ dst, const int M)
{
    constexpr int BM = 128, BN = 64;
    constexpr int NTHR = 256, MT = 2, NT = 4;
    constexpr int ASZ = BM * 72, BSZ = BN * 72;
    constexpr int STG = ASZ + BSZ;
    extern __shared__ char dynsm[];
    __half* smem = (__half*)dynsm;

    const int tid = threadIdx.x, lane = tid & 31, warp = tid >> 5;
    const int bm = blockIdx.y * BM;
    const int bn = blockIdx.x * BN;
    const int wm0 = (warp >> 1) * 32, wn0 = (warp & 1) * 32;
    const uint32_t su = smem_u32(smem);

    const __half* aT;  const float* wsrc;  int roff;
    if (bm < 2048)      { aT = aT0; wsrc = w0; roff = 0; }
    else if (bm < 2560) { aT = aT1; wsrc = w1; roff = 2048; }
    else                { aT = aT2; wsrc = w2; roff = 2560; }

    const int rowA = ((lane >> 3) & 1) * 8 + (lane & 7);
    const int kselA = (lane >> 4) * 8;
    const int rowB = ((lane >> 4) & 1) * 8 + (lane & 7);
    const int kselB = ((lane >> 3) & 1) * 8;

    float acc[MT][NT][4];
#pragma unroll
    for (int i = 0; i < MT; i++)
#pragma unroll
        for (int j = 0; j < NT; j++)
#pragma unroll
            for (int t = 0; t < 4; t++) acc[i][j][t] = 0.f;

    auto load_stage = [&](int st, int k0) {
        uint32_t base = su + (uint32_t)st * STG * 2;
#pragma unroll
        for (int c = tid; c < BM * 8; c += NTHR) {
            int r = c >> 3, sg = c & 7;
            uint32_t so = (uint32_t)(r * 144 + sg * 16);
            CP16(base + so, Ab + (size_t)(bm + r) * 128 + k0 + sg * 8);
        }
#pragma unroll
        for (int c = tid; c < BN * 8; c += NTHR) {
            int r = c >> 3, sg = c & 7;
            uint32_t so = (uint32_t)(r * 144 + sg * 16);
            CP16(base + ASZ * 2 + so, aT + (size_t)(bn + r) * 128 + k0 + sg * 8);
        }
    };

    uint32_t ah[2][MT][4], bh[2][NT][2];

    load_stage(0, 0);
    CP_COMMIT();

    for (int kt = 0; kt < 2; kt++) {
        const int buf = kt & 1;
        if (kt == 0) { load_stage(1, 64); CP_COMMIT(); CP_WAIT1(); }
        else         { CP_WAIT0(); }
        __syncthreads();

        const uint32_t uAh = su + (uint32_t)buf * STG * 2;
        const uint32_t uBh = uAh + ASZ * 2;

        auto ldfrag = [&](int kk, int pb) {
#pragma unroll
            for (int mt = 0; mt < MT; mt++) {
                uint32_t off = (uint32_t)((wm0 + mt*16 + rowA) * 72 + kk*16 + kselA) * 2;
                ldm_x4(ah[pb][mt], uAh + off);
            }
#pragma unroll
            for (int g = 0; g < 2; g++) {
                uint32_t off = (uint32_t)((wn0 + g*16 + rowB) * 72 + kk*16 + kselB) * 2;
                uint32_t r4[4];
                ldm_x4(r4, uBh + off);
                bh[pb][2*g][0] = r4[0]; bh[pb][2*g][1] = r4[1];
                bh[pb][2*g+1][0] = r4[2]; bh[pb][2*g+1][1] = r4[3];
            }
        };

        ldfrag(0, 0);
#pragma unroll
        for (int kk = 0; kk < 4; kk++) {
            const int pb = kk & 1;
            if (kk < 3) ldfrag(kk + 1, (kk + 1) & 1);
#pragma unroll
            for (int mt = 0; mt < MT; mt++)
#pragma unroll
                for (int nt = 0; nt < NT; nt++)
                    mma16816(acc[mt][nt], ah[pb][mt], bh[pb][nt]);
        }
        __syncthreads();
    }

    const int crow = lane >> 2, ccol = (lane & 3) * 2;
#pragma unroll
    for (int mt = 0; mt < MT; mt++) {
#pragma unroll
        for (int nt = 0; nt < NT; nt++) {
            int r0 = bm + wm0 + mt*16 + crow;
            int c0 = bn + wn0 + nt*8 + ccol;
            float2 wv0 = *(const float2*)&wsrc[(size_t)(r0 - roff) * 2048 + c0];
            float2 wv1 = *(const float2*)&wsrc[(size_t)(r0 + 8 - roff) * 2048 + c0];
            *(uint32_t*)&dst[(size_t)r0 * 2048 + c0] =
                packh2(acc[mt][nt][0] + wv0.x, acc[mt][nt][1] + wv0.y);
            *(uint32_t*)&dst[(size_t)(r0+8) * 2048 + c0] =
                packh2(acc[mt][nt][2] + wv1.x, acc[mt][nt][3] + wv1.y);
        }
    }
}

// ============================================================
// main mma.sync GEMM: 128x64 CTA, 8 warps (4x2 of 32x32),
// K-chunk 64 (stride 72), 2-stage cp.async, reg double-buffered.
// MODE 1 (QKV): N=3072, rope epilogue -> qh/kh/vh fp16
// MODE 3 (OUT): N=2048, fp32 out
// ============================================================
template<int MODE>
__global__ void __launch_bounds__(256, 2) gemm_mma(
    const __half* __restrict__ A1, const __half* __restrict__ B1,
    float* __restrict__ F0,
    __half* __restrict__ H0, __half* __restrict__ H1, __half* __restrict__ H2,
    const int M, const int N, const int K)
{
    constexpr int BM = 128, BN = 64;
    constexpr int NTHR = 256, MT = 2, NT = 4;
    constexpr int ASZ = BM * 72, BSZ = BN * 72;
    constexpr int STG = ASZ + BSZ;
    extern __shared__ char dynsm[];
    __half* smem = (__half*)dynsm;

    const int tid = threadIdx.x, lane = tid & 31, warp = tid >> 5;
    const int bm = blockIdx.y * BM;
    const int bn = blockIdx.x * BN;
    const int wm0 = (warp >> 1) * 32, wn0 = (warp & 1) * 32;
    const uint32_t su = smem_u32(smem);

    const int rowA = ((lane >> 3) & 1) * 8 + (lane & 7);
    const int kselA = (lane >> 4) * 8;
    const int rowB = ((lane >> 4) & 1) * 8 + (lane & 7);
    const int kselB = ((lane >> 3) & 1) * 8;

    float acc[MT][NT][4];
#pragma unroll
    for (int i = 0; i < MT; i++)
#pragma unroll
        for (int j = 0; j < NT; j++)
#pragma unroll
            for (int t = 0; t < 4; t++) acc[i][j][t] = 0.f;

    auto load_stage = [&](int st, int k0) {
        uint32_t base = su + (uint32_t)st * STG * 2;
#pragma unroll
        for (int c = tid; c < BM * 8; c += NTHR) {
            int r = c >> 3, sg = c & 7;
            uint32_t so = (uint32_t)(r * 144 + sg * 16);
            CP16(base + so, A1 + (size_t)(bm + r) * 2048 + k0 + sg * 8);
        }
#pragma unroll
        for (int c = tid; c < BN * 8; c += NTHR) {
            int r = c >> 3, sg = c & 7;
            uint32_t so = (uint32_t)(r * 144 + sg * 16);
            CP16(base + ASZ * 2 + so, B1 + (size_t)(bn + r) * 2048 + k0 + sg * 8);
        }
    };

    uint32_t ah[2][MT][4], bh[2][NT][2];

    const int nk = K / 64;
    load_stage(0, 0);
    CP_COMMIT();

    for (int kt = 0; kt < nk; kt++) {
        const int buf = kt & 1;
        if (kt + 1 < nk) {
            load_stage((kt + 1) & 1, (kt + 1) * 64);
            CP_COMMIT();
            CP_WAIT1();
        } else {
            CP_WAIT0();
        }
        __syncthreads();

        const uint32_t uAh = su + (uint32_t)buf * STG * 2;
        const uint32_t uBh = uAh + ASZ * 2;

        auto ldfrag = [&](int kk, int pb) {
#pragma unroll
            for (int mt = 0; mt < MT; mt++) {
                uint32_t off = (uint32_t)((wm0 + mt*16 + rowA) * 72 + kk*16 + kselA) * 2;
                ldm_x4(ah[pb][mt], uAh + off);
            }
#pragma unroll
            for (int g = 0; g < 2; g++) {
                uint32_t off = (uint32_t)((wn0 + g*16 + rowB) * 72 + kk*16 + kselB) * 2;
                uint32_t r4[4];
                ldm_x4(r4, uBh + off);
                bh[pb][2*g][0] = r4[0]; bh[pb][2*g][1] = r4[1];
                bh[pb][2*g+1][0] = r4[2]; bh[pb][2*g+1][1] = r4[3];
            }
        };

        ldfrag(0, 0);
#pragma unroll
        for (int kk = 0; kk < 4; kk++) {
            const int pb = kk & 1;
            if (kk < 3) ldfrag(kk + 1, (kk + 1) & 1);
#pragma unroll
            for (int mt = 0; mt < MT; mt++)
#pragma unroll
                for (int nt = 0; nt < NT; nt++)
                    mma16816(acc[mt][nt], ah[pb][mt], bh[pb][nt]);
        }
        __syncthreads();
    }

    // ---- epilogue ----
    const int crow = lane >> 2, ccol = (lane & 3) * 2;

    if constexpr (MODE == 1) {
        __half* Sh;  int ldcs, col0;  float rscale = 1.f;  bool doRope;
        if (bn < 2048)      { Sh = H0; ldcs = 2048; col0 = bn;        rscale = SCALE; doRope = true; }
        else if (bn < 2560) { Sh = H1; ldcs = 512;  col0 = bn - 2048; doRope = true; }
        else                { Sh = H2; ldcs = 512;  col0 = bn - 2560; doRope = false; }
#pragma unroll
        for (int nt = 0; nt < NT; nt++) {
            int c0 = col0 + wn0 + nt*8 + ccol;
            float invf = 0.f;
            if (doRope) {
                int d = (c0 & 127) >> 1;
                invf = (float)pow(1.0e6, -(double)d / 64.0);
            }
#pragma unroll
            for (int mt = 0; mt < MT; mt++) {
                int r0 = bm + wm0 + mt*16 + crow;
                float v00 = acc[mt][nt][0], v01 = acc[mt][nt][1];
                float v10 = acc[mt][nt][2], v11 = acc[mt][nt][3];
                if (doRope) {
                    float sn, cs;
                    sincosf((float)(r0 & 2047) * invf, &sn, &cs);
                    float a0 = (v00*cs - v01*sn) * rscale;
                    float a1 = (v00*sn + v01*cs) * rscale;
                    *(uint32_t*)&Sh[(size_t)r0 * ldcs + c0] = packh2(a0, a1);
                    sincosf((float)((r0+8) & 2047) * invf, &sn, &cs);
                    a0 = (v10*cs - v11*sn) * rscale;
                    a1 = (v10*sn + v11*cs) * rscale;
                    *(uint32_t*)&Sh[(size_t)(r0+8) * ldcs + c0] = packh2(a0, a1);
                } else {
                    *(uint32_t*)&Sh[(size_t)r0 * ldcs + c0]     = packh2(v00, v01);
                    *(uint32_t*)&Sh[(size_t)(r0+8) * ldcs + c0] = packh2(v10, v11);
                }
            }
        }
    } else {
#pragma unroll
        for (int mt = 0; mt < MT; mt++) {
#pragma unroll
            for (int nt = 0; nt < NT; nt++) {
                int r0 = bm + wm0 + mt*16 + crow;
                int c0 = bn + wn0 + nt*8 + ccol;
                *(float2*)&F0[(size_t)r0 * 2048 + c0] =
                    make_float2(acc[mt][nt][0], acc[mt][nt][1]);
                *(float2*)&F0[(size_t)(r0+8) * 2048 + c0] =
                    make_float2(acc[mt][nt][2], acc[mt][nt][3]);
            }
        }
    }
}

// ============================================================
// Tensor-core flash attention — single-pass fp16 (unchanged).
// ============================================================
static constexpr int AQ_H = 0;
static constexpr int ASTG = 17408;
static constexpr int AVH = 8704;
static constexpr int ATTN_SMEM_BYTES = (17408 + 2 * ASTG) * 2;  // 104448

__global__ void __launch_bounds__(256, 2) attn_mma_kernel(
    const __half* __restrict__ qh,
    const __half* __restrict__ kh,
    const __half* __restrict__ vh,
    __half* __restrict__ aoh)
{
    extern __shared__ char dynsm[];
    __half* sm = (__half*)dynsm;
    const int qb = blockIdx.x, h = blockIdx.y, b = blockIdx.z;
    const int i0 = qb * 128;
    const int tid = threadIdx.x, lane = tid & 31, warp = tid >> 5;
    const int kvh = h >> 2;
    const uint32_t su = smem_u32(sm);

#pragma unroll
    for (int c = tid; c < 128 * 16; c += 256) {
        int r = c >> 4, sg = c & 15;
        size_t g = ((size_t)(b*S + i0 + r)) * (H*HD) + h*HD + sg*8;
        *(uint4*)&sm[AQ_H + r*136 + sg*8] = *(const uint4*)(qh + g);
    }

    float O[16][4];
#pragma unroll
    for (int i = 0; i < 16; i++)
#pragma unroll
        for (int t = 0; t < 4; t++) O[i][t] = 0.f;
    float m0 = -1e30f, m1 = -1e30f, l0 = 0.f, l1 = 0.f;

    const int rowA = ((lane >> 3) & 1) * 8 + (lane & 7);
    const int kselA = (lane >> 4) * 8;
    const int rowB = ((lane >> 4) & 1) * 8 + (lane & 7);
    const int kselB = ((lane >> 3) & 1) * 8;
    const int rowV = ((lane >> 3) & 1) * 8 + (lane & 7);
    const int colV = (lane >> 4) * 8;

    int startb = 2*qb - 8; if (startb < 1) startb = 1;
    const int kb_end = 2*qb + 1;
    const int nblk = 1 + (kb_end - startb + 1);

    const int ir0 = i0 + warp*16 + (lane >> 2);
    const int ir1 = ir0 + 8;

    auto kbof = [&](int i) { return (i == 0) ? 0 : (startb + i - 1); };
    auto load_kv = [&](int st, int kb) {
        uint32_t base = su + (uint32_t)(17408 + ASTG * st) * 2;
#pragma unroll
        for (int c = tid; c < 64 * 16; c += 256) {
            int r = c >> 4, sg = c & 15;
            size_t g = ((size_t)(b*S + kb*64 + r)) * (KVH*HD) + kvh*HD + sg*8;
            uint32_t so = (uint32_t)(r*136 + sg*8) * 2;
            CP16(base + so, kh + g);
            CP16(base + AVH*2 + so, vh + g);
        }
    };

    load_kv(0, kbof(0));
    CP_COMMIT();
    if (nblk > 1) { load_kv(1, kbof(1)); CP_COMMIT(); }

    for (int bi = 0; bi < nblk; bi++) {
        if (bi + 1 < nblk) CP_WAIT1(); else CP_WAIT0();
        __syncthreads();
        const int kb = kbof(bi);
        const uint32_t sb2 = su + (uint32_t)(17408 + ASTG * (bi & 1)) * 2;

        float sc[8][4];
#pragma unroll
        for (int i = 0; i < 8; i++)
#pragma unroll
            for (int t = 0; t < 4; t++) sc[i][t] = 0.f;

#pragma unroll
        for (int kk = 0; kk < 8; kk++) {
            uint32_t ah[4];
            uint32_t offA = (uint32_t)((warp*16 + rowA)*136 + kk*16 + kselA) * 2;
            ldm_x4(ah, su + AQ_H*2 + offA);
#pragma unroll
            for (int g2 = 0; g2 < 4; g2++) {
                uint32_t bh4[4];
                uint32_t offB = (uint32_t)((g2*16 + rowB)*136 + kk*16 + kselB) * 2;
                ldm_x4(bh4, sb2 + offB);
                mma16816(sc[2*g2],   ah, bh4);
                mma16816(sc[2*g2+1], ah, bh4 + 2);
            }
        }

        const int jb = kb*64 + (lane & 3) * 2;
        float mx0 = -1e30f, mx1 = -1e30f;
#pragma unroll
        for (int nt = 0; nt < 8; nt++) {
            int j0 = jb + nt*8, j1 = j0 + 1;
            if (!((j0 <= ir0) && (((ir0 - j0) < WINDOW) || (j0 < GLOBALK)))) sc[nt][0] = -1e30f;
            if (!((j1 <= ir0) && (((ir0 - j1) < WINDOW) || (j1 < GLOBALK)))) sc[nt][1] = -1e30f;
            if (!((j0 <= ir1) && (((ir1 - j0) < WINDOW) || (j0 < GLOBALK)))) sc[nt][2] = -1e30f;
            if (!((j1 <= ir1) && (((ir1 - j1) < WINDOW) || (j1 < GLOBALK)))) sc[nt][3] = -1e30f;
            mx0 = fmaxf(mx0, fmaxf(sc[nt][0], sc[nt][1]));
            mx1 = fmaxf(mx1, fmaxf(sc[nt][2], sc[nt][3]));
        }
        mx0 = fmaxf(mx0, __shfl_xor_sync(0xffffffffu, mx0, 1));
        mx0 = fmaxf(mx0, __shfl_xor_sync(0xffffffffu, mx0, 2));
        mx1 = fmaxf(mx1, __shfl_xor_sync(0xffffffffu, mx1, 1));
        mx1 = fmaxf(mx1, __shfl_xor_sync(0xffffffffu, mx1, 2));

        float nm0 = fmaxf(m0, mx0), nm1 = fmaxf(m1, mx1);
        float a0 = __expf(m0 - nm0), a1 = __expf(m1 - nm1);
        float s0 = 0.f, s1 = 0.f;
#pragma unroll
        for (int nt = 0; nt < 8; nt++) {
            sc[nt][0] = __expf(sc[nt][0] - nm0);
            sc[nt][1] = __expf(sc[nt][1] - nm0);
            sc[nt][2] = __expf(sc[nt][2] - nm1);
            sc[nt][3] = __expf(sc[nt][3] - nm1);
            s0 += sc[nt][0] + sc[nt][1];
            s1 += sc[nt][2] + sc[nt][3];
        }
        s0 += __shfl_xor_sync(0xffffffffu, s0, 1);
        s0 += __shfl_xor_sync(0xffffffffu, s0, 2);
        s1 += __shfl_xor_sync(0xffffffffu, s1, 1);
        s1 += __shfl_xor_sync(0xffffffffu, s1, 2);
        l0 = l0 * a0 + s0;  l1 = l1 * a1 + s1;
        m0 = nm0;  m1 = nm1;
#pragma unroll
        for (int dt = 0; dt < 16; dt++) {
            O[dt][0] *= a0; O[dt][1] *= a0;
            O[dt][2] *= a1; O[dt][3] *= a1;
        }

#pragma unroll
        for (int kk = 0; kk < 4; kk++) {
            uint32_t pah[4];
            pah[0] = packh2(sc[2*kk][0],   sc[2*kk][1]);
            pah[1] = packh2(sc[2*kk][2],   sc[2*kk][3]);
            pah[2] = packh2(sc[2*kk+1][0], sc[2*kk+1][1]);
            pah[3] = packh2(sc[2*kk+1][2], sc[2*kk+1][3]);
#pragma unroll
            for (int dt2 = 0; dt2 < 8; dt2++) {
                uint32_t vbh[4];
                uint32_t offV = (uint32_t)((kk*16 + rowV)*136 + dt2*16 + colV) * 2;
                ldm_x4_t(vbh, sb2 + AVH*2 + offV);
                mma16816(O[2*dt2],   pah, vbh);
                mma16816(O[2*dt2+1], pah, vbh + 2);
            }
        }

        __syncthreads();
        if (bi + 2 < nblk) { load_kv(bi & 1, kbof(bi + 2)); CP_COMMIT(); }
    }

    const float inv0 = 1.f / l0, inv1 = 1.f / l1;
    const size_t rbase0 = ((size_t)(b*S + i0 + warp*16 + (lane >> 2))) * (H*HD);
    const size_t rbase1 = rbase0 + 8 * (size_t)(H*HD);
#pragma unroll
    for (int dt = 0; dt < 16; dt++) {
        int cc = h*HD + dt*8 + (lane & 3) * 2;
        *(uint32_t*)&aoh[rbase0 + cc] = packh2(O[dt][0]*inv0, O[dt][1]*inv0);
        *(uint32_t*)&aoh[rbase1 + cc] = packh2(O[dt][2]*inv1, O[dt][3]*inv1);
    }
}

// ============================================================
// Host side
// ============================================================
static constexpr int SMEM_GEMM = 2 * (128*72 + 64*72) * 2;   // 55296

extern "C" void kernel_launch(void* const* d_in, const int* in_sizes, int n_in,
                              void* d_out, int out_size)
{
    const float* x = (const float*)d_in[0];
    float* out = (float*)d_out;

    __half *xh, *wh, *aoh, *qhp, *khp, *vhp;
    cudaGetSymbolAddress((void**)&xh,  g_xh);
    cudaGetSymbolAddress((void**)&wh,  g_wh);
    cudaGetSymbolAddress((void**)&aoh, g_aoh);
    cudaGetSymbolAddress((void**)&qhp, g_qh);
    cudaGetSymbolAddress((void**)&khp, g_kh);
    cudaGetSymbolAddress((void**)&vhp, g_vh);

    auto G1 = gemm_mma<1>;
    auto G3 = gemm_mma<3>;

    cudaFuncSetAttribute(wfuse_mma, cudaFuncAttributeMaxDynamicSharedMemorySize, SMEM_GEMM);
    cudaFuncSetAttribute(G1, cudaFuncAttributeMaxDynamicSharedMemorySize, SMEM_GEMM);
    cudaFuncSetAttribute(G3, cudaFuncAttributeMaxDynamicSharedMemorySize, SMEM_GEMM);
    cudaFuncSetAttribute(attn_mma_kernel,
        cudaFuncAttributeMaxDynamicSharedMemorySize, ATTN_SMEM_BYTES);

    const int M = MROWS;

    // ---- converts ----
    cvtx_kernel<<<(M*D/4 + 255)/256, 256>>>(x, xh, M*D/4);
    // b-matrices: qb(d_in[3]) kb(6) vb(9) ob(12)
    cvtb_kernel<<<(163840 + 255)/256, 256>>>(
        (const float*)d_in[3], (const float*)d_in[6],
        (const float*)d_in[9], (const float*)d_in[12], wh);
    // a-matrices transpose: qa(2) ka(5) va(8) oa(11)
    {
        dim3 grid(2048/32, 128/32, 4);
        transA_kernel<<<grid, dim3(32, 8)>>>(
            (const float*)d_in[2], (const float*)d_in[5],
            (const float*)d_in[8], (const float*)d_in[11], wh);
    }

    // ---- weight fusion: W_eff = W + B*A ----
    wfuse_mma<<<dim3(2048/64, 3072/128), 256, SMEM_GEMM>>>(
        wh + OFF_QB,
        wh + OFF_A, wh + OFF_A + 262144, wh + OFF_A + 524288,
        (const float*)d_in[1], (const float*)d_in[4], (const float*)d_in[7],
        wh + OFF_QKVW, 3072);
    wfuse_mma<<<dim3(2048/64, 2048/128), 256, SMEM_GEMM>>>(
        wh + OFF_OB,
        wh + OFF_OAT, wh + OFF_OAT, wh + OFF_OAT,
        (const float*)d_in[10], (const float*)d_in[10], (const float*)d_in[10],
        wh + OFF_OW, 2048);

    // ---- G1: qh|kh|vh = rope(x @ W_eff_qkv^T) ----
    G1<<<dim3(3072/64, 32), 256, SMEM_GEMM>>>(
        xh, wh + OFF_QKVW, nullptr, qhp, khp, vhp, M, 3072, 2048);

    // ---- attention (single-pass fp16) ----
    {
        dim3 grid(S/128, H, B);
        attn_mma_kernel<<<grid, 256, ATTN_SMEM_BYTES>>>(qhp, khp, vhp, aoh);
    }

    // ---- G3: out = ao @ W_eff_o^T (fp32) ----
    G3<<<dim3(2048/64, 32), 256, SMEM_GEMM>>>(
        aoh, wh + OFF_OW, out, nullptr, nullptr, nullptr, M, 2048, 2048);
}